// round 9
// baseline (speedup 1.0000x reference)
#include <cuda_runtime.h>
#include <cuda_bf16.h>
#include <math.h>
#include <stdint.h>

#define NN 50000
#define EE 800000
#define HIDC 128
#define FFC 256
#define NLAYERS 6
#define EPSLN 1e-5f

// ---------------- scratch (device globals; no allocation allowed) ----------------
__device__ float g_z[NN * HIDC];
__device__ float g_q[NN * HIDC];
__device__ unsigned g_kh[NN * (HIDC / 2)];   // bf16x2 packed K
__device__ unsigned g_vh[NN * (HIDC / 2)];   // bf16x2 packed V
__device__ float g_sk[NN * HIDC];
__device__ float g_attn[NN * HIDC];
__device__ float g_h[NN * HIDC];
__device__ float g_t[NN * FFC];
__device__ float g_u[NN * HIDC];
__device__ int g_src[EE];
__device__ int g_dst[EE];
__device__ int g_deg[NN];
__device__ int g_rowptr[NN + 1];
__device__ int g_cur[NN];
__device__ int g_csrc[EE];
__device__ int g_csums[128];
__device__ float g_betas[NLAYERS + 2];
__device__ int g_flag[1];

// tf32-preconverted weights (original [K,N] layout)
#define OFF_WQ  16384
#define OFF_WK  (OFF_WQ + NLAYERS * HIDC * HIDC)
#define OFF_WV  (OFF_WK + NLAYERS * HIDC * HIDC)
#define OFF_WSK (OFF_WV + NLAYERS * HIDC * HIDC)
#define OFF_W1  (OFF_WSK + NLAYERS * HIDC * HIDC)
#define OFF_W2  (OFF_W1 + NLAYERS * HIDC * FFC)
#define TOTW    (OFF_W2 + NLAYERS * FFC * HIDC)
__device__ float g_wt[TOTW];

#define CHUNK 512
#define NCHK ((NN + CHUNK - 1) / CHUNK)   // 98

// ---------------- helpers ----------------
__device__ __forceinline__ uint32_t f2tf32(float x) {
    uint32_t r;
    asm("cvt.rna.tf32.f32 %0, %1;" : "=r"(r) : "f"(x));
    return r;
}

__device__ __forceinline__ void mma_tf32(float* d, const uint32_t* a, const uint32_t* b) {
    asm volatile(
        "mma.sync.aligned.m16n8k8.row.col.f32.tf32.tf32.f32 "
        "{%0,%1,%2,%3}, {%4,%5,%6,%7}, {%8,%9}, {%0,%1,%2,%3};"
        : "+f"(d[0]), "+f"(d[1]), "+f"(d[2]), "+f"(d[3])
        : "r"(a[0]), "r"(a[1]), "r"(a[2]), "r"(a[3]), "r"(b[0]), "r"(b[1]));
}

__device__ __forceinline__ void cp16(uint32_t saddr, const void* g) {
    asm volatile("cp.async.ca.shared.global [%0], [%1], 16;" ::"r"(saddr), "l"(g));
}
__device__ __forceinline__ void cp_commit() {
    asm volatile("cp.async.commit_group;");
}
__device__ __forceinline__ void cp_wait0() {
    asm volatile("cp.async.wait_group 0;");
}

// ---------------- edge index dtype sniff + convert ----------------
__global__ void sniff_kernel(const unsigned* __restrict__ w) {
    if (threadIdx.x == 0 && blockIdx.x == 0) {
        int is64 = 1;
        for (int i = 1; i < 64; i += 2)
            if (w[i] != 0u) { is64 = 0; break; }
        g_flag[0] = is64;
    }
}

__global__ __launch_bounds__(256) void convert_edges(const void* __restrict__ ei) {
    int e = blockIdx.x * blockDim.x + threadIdx.x;
    if (e >= EE) return;
    if (g_flag[0]) {
        const long long* p = (const long long*)ei;
        g_src[e] = (int)p[e];
        g_dst[e] = (int)p[EE + e];
    } else {
        const int* p = (const int*)ei;
        g_src[e] = p[e];
        g_dst[e] = p[EE + e];
    }
}

__global__ void beta_softmax(const float* __restrict__ beta) {
    if (threadIdx.x == 0 && blockIdx.x == 0) {
        float m = -1e30f;
        for (int i = 0; i < NLAYERS + 1; i++) m = fmaxf(m, beta[i]);
        float s = 0.f;
        for (int i = 0; i < NLAYERS + 1; i++) {
            float e = expf(beta[i] - m);
            g_betas[i] = e;
            s += e;
        }
        for (int i = 0; i < NLAYERS + 1; i++) g_betas[i] /= s;
    }
}

// ---------------- one-shot weight tf32 preconversion ----------------
__global__ __launch_bounds__(256) void convW(
    const float* __restrict__ Win, const float* __restrict__ Wq,
    const float* __restrict__ Wk, const float* __restrict__ Wv,
    const float* __restrict__ Wsk, const float* __restrict__ W1,
    const float* __restrict__ W2) {
    int i = blockIdx.x * blockDim.x + threadIdx.x;
    if (i >= TOTW) return;
    const float* src;
    int off;
    if (i < OFF_WQ)       { src = Win; off = i; }
    else if (i < OFF_WK)  { src = Wq;  off = i - OFF_WQ; }
    else if (i < OFF_WV)  { src = Wk;  off = i - OFF_WK; }
    else if (i < OFF_WSK) { src = Wv;  off = i - OFF_WV; }
    else if (i < OFF_W1)  { src = Wsk; off = i - OFF_WSK; }
    else if (i < OFF_W2)  { src = W1;  off = i - OFF_W1; }
    else                  { src = W2;  off = i - OFF_W2; }
    g_wt[i] = __uint_as_float(f2tf32(src[off]));
}

// ---------------- CSR build ----------------
__global__ __launch_bounds__(256) void k_clear_deg() {
    int i = blockIdx.x * blockDim.x + threadIdx.x;
    if (i < NN) g_deg[i] = 0;
}
__global__ __launch_bounds__(256) void k_hist() {
    int e = blockIdx.x * blockDim.x + threadIdx.x;
    if (e < EE) atomicAdd(&g_deg[g_dst[e]], 1);
}
__global__ __launch_bounds__(CHUNK) void k_chunksum() {
    __shared__ int sh[CHUNK];
    int tid = threadIdx.x;
    int i = blockIdx.x * CHUNK + tid;
    sh[tid] = (i < NN) ? g_deg[i] : 0;
    __syncthreads();
    for (int off = CHUNK / 2; off > 0; off >>= 1) {
        if (tid < off) sh[tid] += sh[tid + off];
        __syncthreads();
    }
    if (tid == 0) g_csums[blockIdx.x] = sh[0];
}
__global__ void k_scanchunks() {
    if (threadIdx.x == 0 && blockIdx.x == 0) {
        int run = 0;
        for (int c = 0; c < NCHK; c++) {
            int v = g_csums[c];
            g_csums[c] = run;
            run += v;
        }
        g_rowptr[NN] = run;
    }
}
__global__ __launch_bounds__(CHUNK) void k_rowptr() {
    __shared__ int sh[CHUNK];
    int tid = threadIdx.x;
    int i = blockIdx.x * CHUNK + tid;
    int v = (i < NN) ? g_deg[i] : 0;
    sh[tid] = v;
    __syncthreads();
    for (int off = 1; off < CHUNK; off <<= 1) {
        int t = (tid >= off) ? sh[tid - off] : 0;
        __syncthreads();
        sh[tid] += t;
        __syncthreads();
    }
    if (i < NN) {
        int excl = sh[tid] - v + g_csums[blockIdx.x];
        g_rowptr[i] = excl;
        g_cur[i] = excl;
    }
}
__global__ __launch_bounds__(256) void k_fill() {
    int e = blockIdx.x * blockDim.x + threadIdx.x;
    if (e >= EE) return;
    int slot = atomicAdd(&g_cur[g_dst[e]], 1);
    g_csrc[slot] = g_src[e];
}

// ---------------- TF32 GEMM: 256 thr, 8 warps (2x4), warp tile 64x32 ----------
#define BM 128
#define BN 128
#define BK 16

__device__ __forceinline__ void ldA(
    const float* __restrict__ A, int M, int K, int m0, int kc, int tid,
    float4 ar[2]) {
#pragma unroll
    for (int i = 0; i < 2; i++) {
        int f = tid + i * 256;
        int m = f >> 2, k4 = (f & 3) * 4;
        ar[i] = (m0 + m < M)
                    ? *(const float4*)(A + (size_t)(m0 + m) * K + kc + k4)
                    : make_float4(0.f, 0.f, 0.f, 0.f);
    }
}

__device__ __forceinline__ void stA(float (*As)[BK + 4], int tid,
                                    const float4 ar[2]) {
#pragma unroll
    for (int i = 0; i < 2; i++) {
        int f = tid + i * 256;
        int m = f >> 2, k4 = (f & 3) * 4;
        float4 cv;
        cv.x = __uint_as_float(f2tf32(ar[i].x));
        cv.y = __uint_as_float(f2tf32(ar[i].y));
        cv.z = __uint_as_float(f2tf32(ar[i].z));
        cv.w = __uint_as_float(f2tf32(ar[i].w));
        *(float4*)&As[m][k4] = cv;
    }
}

__device__ __forceinline__ void cpB(float (*Bs)[BN + 8],
                                    const float* __restrict__ B, int Nld,
                                    int n0, int kc, int tid) {
#pragma unroll
    for (int i = 0; i < 2; i++) {
        int f = tid + i * 256;
        int k = f >> 5, n4 = (f & 31) * 4;
        uint32_t sa = (uint32_t)__cvta_generic_to_shared(&Bs[k][n4]);
        cp16(sa, B + (size_t)(kc + k) * Nld + n0 + n4);
    }
}

// out mode: 0 = fp32 C, 1 = bf16x2 packed C (Nld must be full row width)
template <int ACT>
__device__ __forceinline__ void gemm_core(
    const float* __restrict__ A, const float* __restrict__ B,
    const float* __restrict__ bias, void* __restrict__ Cv,
    int M, int K, int Nld, int m0, int n0, int bf16out,
    float As[2][BM][BK + 4], float Bs[2][BK][BN + 8]) {
    int tid = threadIdx.x;
    int warp = tid >> 5, lane = tid & 31;
    int wm = (warp >> 2) * 64, wn = (warp & 3) * 32;
    int g = lane >> 2, t = lane & 3;

    float acc[4][4][4];
#pragma unroll
    for (int a = 0; a < 4; a++)
#pragma unroll
        for (int b = 0; b < 4; b++)
#pragma unroll
            for (int c = 0; c < 4; c++) acc[a][b][c] = 0.f;

    float4 ar[2];
    ldA(A, M, K, m0, 0, tid, ar);
    cpB(Bs[0], B, Nld, n0, 0, tid);
    stA(As[0], tid, ar);
    cp_commit();
    cp_wait0();
    __syncthreads();

    int nit = K / BK;
    for (int it = 0; it < nit; it++) {
        int cur = it & 1;
        if (it + 1 < nit) {
            ldA(A, M, K, m0, (it + 1) * BK, tid, ar);
            cpB(Bs[cur ^ 1], B, Nld, n0, (it + 1) * BK, tid);
            cp_commit();
        }

#pragma unroll
        for (int kk = 0; kk < BK; kk += 8) {
            uint32_t af[4][4];
#pragma unroll
            for (int tm = 0; tm < 4; tm++) {
                int mb = wm + tm * 16;
                af[tm][0] = __float_as_uint(As[cur][mb + g][kk + t]);
                af[tm][1] = __float_as_uint(As[cur][mb + g + 8][kk + t]);
                af[tm][2] = __float_as_uint(As[cur][mb + g][kk + t + 4]);
                af[tm][3] = __float_as_uint(As[cur][mb + g + 8][kk + t + 4]);
            }
            uint32_t bf[4][2];
#pragma unroll
            for (int tn = 0; tn < 4; tn++) {
                int nb = wn + tn * 8;
                bf[tn][0] = __float_as_uint(Bs[cur][kk + t][nb + g]);
                bf[tn][1] = __float_as_uint(Bs[cur][kk + t + 4][nb + g]);
            }
#pragma unroll
            for (int tm = 0; tm < 4; tm++)
#pragma unroll
                for (int tn = 0; tn < 4; tn++)
                    mma_tf32(acc[tm][tn], af[tm], bf[tn]);
        }

        if (it + 1 < nit) stA(As[cur ^ 1], tid, ar);
        cp_wait0();
        __syncthreads();
    }

    // epilogue
#pragma unroll
    for (int tm = 0; tm < 4; tm++) {
        int r0 = m0 + wm + tm * 16 + g;
        int r1 = r0 + 8;
#pragma unroll
        for (int tn = 0; tn < 4; tn++) {
            int cb = n0 + wn + tn * 8 + 2 * t;
            float b0 = __ldg(bias + cb);
            float b1 = __ldg(bias + cb + 1);
            float v00 = acc[tm][tn][0] + b0;
            float v01 = acc[tm][tn][1] + b1;
            float v10 = acc[tm][tn][2] + b0;
            float v11 = acc[tm][tn][3] + b1;
            if (ACT == 1) {
                v00 = fmaxf(v00, 0.f); v01 = fmaxf(v01, 0.f);
                v10 = fmaxf(v10, 0.f); v11 = fmaxf(v11, 0.f);
            }
            if (ACT == 2) {
                v00 = 0.5f * v00 * (1.f + erff(v00 * 0.70710678118654752f));
                v01 = 0.5f * v01 * (1.f + erff(v01 * 0.70710678118654752f));
                v10 = 0.5f * v10 * (1.f + erff(v10 * 0.70710678118654752f));
                v11 = 0.5f * v11 * (1.f + erff(v11 * 0.70710678118654752f));
            }
            if (!bf16out) {
                float* C = (float*)Cv;
                if (r0 < M) *(float2*)(C + (size_t)r0 * Nld + cb) = make_float2(v00, v01);
                if (r1 < M) *(float2*)(C + (size_t)r1 * Nld + cb) = make_float2(v10, v11);
            } else {
                unsigned* C = (unsigned*)Cv;
                __nv_bfloat162 h0 = __float22bfloat162_rn(make_float2(v00, v01));
                __nv_bfloat162 h1 = __float22bfloat162_rn(make_float2(v10, v11));
                int half_pitch = Nld >> 1;
                if (r0 < M) C[(size_t)r0 * half_pitch + (cb >> 1)] = *(unsigned*)&h0;
                if (r1 < M) C[(size_t)r1 * half_pitch + (cb >> 1)] = *(unsigned*)&h1;
            }
        }
    }
}

template <int ACT>
__global__ __launch_bounds__(256, 2) void gemm_tf32(
    const float* __restrict__ A, const float* __restrict__ B,
    const float* __restrict__ bias, float* __restrict__ C,
    int M, int K, int Nld) {
    __shared__ __align__(16) float As[2][BM][BK + 4];
    __shared__ __align__(16) float Bs[2][BK][BN + 8];
    gemm_core<ACT>(A, B, bias, C, M, K, Nld, blockIdx.x * BM, blockIdx.y * BN,
                   0, As, Bs);
}

// fused Q/K/V/SK projection: grid.y in [0,4) selects operator
// K and V outputs are written as packed bf16x2 into g_kh/g_vh.
__global__ __launch_bounds__(256, 2) void gemm_qkvsk(
    const float* __restrict__ A, const float* __restrict__ wt,
    const float* __restrict__ bq, const float* __restrict__ bk,
    const float* __restrict__ bv, const float* __restrict__ bsk, int l) {
    __shared__ __align__(16) float As[2][BM][BK + 4];
    __shared__ __align__(16) float Bs[2][BK][BN + 8];
    const float* B;
    const float* bias;
    void* C;
    int bf16out;
    switch (blockIdx.y) {
        case 0: B = wt + OFF_WQ;  bias = bq;  C = (void*)g_q;  bf16out = 0; break;
        case 1: B = wt + OFF_WK;  bias = bk;  C = (void*)g_kh; bf16out = 1; break;
        case 2: B = wt + OFF_WV;  bias = bv;  C = (void*)g_vh; bf16out = 1; break;
        default: B = wt + OFF_WSK; bias = bsk; C = (void*)g_sk; bf16out = 0; break;
    }
    B += (size_t)l * HIDC * HIDC;
    bias += l * HIDC;
    gemm_core<0>(A, B, bias, C, NN, HIDC, HIDC, blockIdx.x * BM, 0, bf16out,
                 As, Bs);
}

// ---------------- fused attention: warp/node, online softmax, bf16 K/V --------
__global__ __launch_bounds__(256) void attn_fused() {
    int node = (blockIdx.x * blockDim.x + threadIdx.x) >> 5;
    if (node >= NN) return;
    int lane = threadIdx.x & 31;
    int beg = g_rowptr[node], end = g_rowptr[node + 1];
    size_t qb = (size_t)node * HIDC + lane * 4;
    float4 qv = *(const float4*)(g_q + qb);
    const uint2* khp = (const uint2*)g_kh;  // row pitch 32 uint2
    const uint2* vhp = (const uint2*)g_vh;
    float m = -INFINITY, l = 0.f;
    float4 acc = make_float4(0.f, 0.f, 0.f, 0.f);
    int e = beg;
    for (; e + 1 < end; e += 2) {
        int s0 = g_csrc[e], s1 = g_csrc[e + 1];
        size_t b0 = (size_t)s0 * 32 + lane;
        size_t b1 = (size_t)s1 * 32 + lane;
        uint2 kr0 = khp[b0];
        uint2 kr1 = khp[b1];
        uint2 vr0 = vhp[b0];
        uint2 vr1 = vhp[b1];
        float2 ka0 = __bfloat1622float2(*(__nv_bfloat162*)&kr0.x);
        float2 kb0 = __bfloat1622float2(*(__nv_bfloat162*)&kr0.y);
        float2 ka1 = __bfloat1622float2(*(__nv_bfloat162*)&kr1.x);
        float2 kb1 = __bfloat1622float2(*(__nv_bfloat162*)&kr1.y);
        float p0 = qv.x * ka0.x + qv.y * ka0.y + qv.z * kb0.x + qv.w * kb0.y;
        float p1 = qv.x * ka1.x + qv.y * ka1.y + qv.z * kb1.x + qv.w * kb1.y;
        p0 += __shfl_xor_sync(0xffffffffu, p0, 8, 16);
        p1 += __shfl_xor_sync(0xffffffffu, p1, 8, 16);
        p0 += __shfl_xor_sync(0xffffffffu, p0, 4, 16);
        p1 += __shfl_xor_sync(0xffffffffu, p1, 4, 16);
        p0 += __shfl_xor_sync(0xffffffffu, p0, 2, 16);
        p1 += __shfl_xor_sync(0xffffffffu, p1, 2, 16);
        p0 += __shfl_xor_sync(0xffffffffu, p0, 1, 16);
        p1 += __shfl_xor_sync(0xffffffffu, p1, 1, 16);
        float sc0 = p0 * 0.125f;
        float sc1 = p1 * 0.125f;
        float mn = fmaxf(m, fmaxf(sc0, sc1));
        float scale = __expf(m - mn);
        float w0 = __expf(sc0 - mn);
        float w1 = __expf(sc1 - mn);
        float2 va0 = __bfloat1622float2(*(__nv_bfloat162*)&vr0.x);
        float2 vb0 = __bfloat1622float2(*(__nv_bfloat162*)&vr0.y);
        float2 va1 = __bfloat1622float2(*(__nv_bfloat162*)&vr1.x);
        float2 vb1 = __bfloat1622float2(*(__nv_bfloat162*)&vr1.y);
        l = l * scale + w0 + w1;
        acc.x = acc.x * scale + w0 * va0.x + w1 * va1.x;
        acc.y = acc.y * scale + w0 * va0.y + w1 * va1.y;
        acc.z = acc.z * scale + w0 * vb0.x + w1 * vb1.x;
        acc.w = acc.w * scale + w0 * vb0.y + w1 * vb1.y;
        m = mn;
    }
    if (e < end) {
        int s = g_csrc[e];
        size_t sb = (size_t)s * 32 + lane;
        uint2 kr = khp[sb];
        uint2 vr = vhp[sb];
        float2 ka = __bfloat1622float2(*(__nv_bfloat162*)&kr.x);
        float2 kb = __bfloat1622float2(*(__nv_bfloat162*)&kr.y);
        float p = qv.x * ka.x + qv.y * ka.y + qv.z * kb.x + qv.w * kb.y;
        p += __shfl_xor_sync(0xffffffffu, p, 8, 16);
        p += __shfl_xor_sync(0xffffffffu, p, 4, 16);
        p += __shfl_xor_sync(0xffffffffu, p, 2, 16);
        p += __shfl_xor_sync(0xffffffffu, p, 1, 16);
        float sc = p * 0.125f;
        float mn = fmaxf(m, sc);
        float scale = __expf(m - mn);
        float w = __expf(sc - mn);
        float2 va = __bfloat1622float2(*(__nv_bfloat162*)&vr.x);
        float2 vb = __bfloat1622float2(*(__nv_bfloat162*)&vr.y);
        l = l * scale + w;
        acc.x = acc.x * scale + w * va.x;
        acc.y = acc.y * scale + w * va.y;
        acc.z = acc.z * scale + w * vb.x;
        acc.w = acc.w * scale + w * vb.y;
    }
    float inv = (l > 0.f) ? 1.f / l : 0.f;
    acc.x *= inv; acc.y *= inv; acc.z *= inv; acc.w *= inv;
    *(float4*)(g_attn + qb) = acc;
}

// ---------------- layernorm kernels (warp per row, 128 cols) ----------------
__global__ __launch_bounds__(256) void ln3_kernel(
    const float* __restrict__ g, const float* __restrict__ bt) {
    int row = (blockIdx.x * blockDim.x + threadIdx.x) >> 5;
    if (row >= NN) return;
    int lane = threadIdx.x & 31;
    size_t base = (size_t)row * HIDC + lane * 4;
    float4 a = *(const float4*)(g_z + base);
    float4 b = *(const float4*)(g_attn + base);
    float4 c = *(const float4*)(g_sk + base);
    float v0 = a.x + b.x + c.x, v1 = a.y + b.y + c.y;
    float v2 = a.z + b.z + c.z, v3 = a.w + b.w + c.w;
    float s = v0 + v1 + v2 + v3;
#pragma unroll
    for (int o = 16; o > 0; o >>= 1) s += __shfl_xor_sync(0xffffffffu, s, o);
    float mu = s * (1.f / HIDC);
    float d0 = v0 - mu, d1 = v1 - mu, d2 = v2 - mu, d3 = v3 - mu;
    float ss = d0 * d0 + d1 * d1 + d2 * d2 + d3 * d3;
#pragma unroll
    for (int o = 16; o > 0; o >>= 1) ss += __shfl_xor_sync(0xffffffffu, ss, o);
    float rs = rsqrtf(ss * (1.f / HIDC) + EPSLN);
    int col = lane * 4;
    float4 o4;
    o4.x = d0 * rs * g[col + 0] + bt[col + 0];
    o4.y = d1 * rs * g[col + 1] + bt[col + 1];
    o4.z = d2 * rs * g[col + 2] + bt[col + 2];
    o4.w = d3 * rs * g[col + 3] + bt[col + 3];
    *(float4*)(g_h + base) = o4;
}

// z = relu(LN(h+u)); out += betas[li]*z
__global__ __launch_bounds__(256) void lnacc_kernel(
    const float* __restrict__ g, const float* __restrict__ bt,
    float* __restrict__ out, int li) {
    int row = (blockIdx.x * blockDim.x + threadIdx.x) >> 5;
    if (row >= NN) return;
    int lane = threadIdx.x & 31;
    size_t base = (size_t)row * HIDC + lane * 4;
    float4 a = *(const float4*)(g_h + base);
    float4 b = *(const float4*)(g_u + base);
    float v0 = a.x + b.x, v1 = a.y + b.y, v2 = a.z + b.z, v3 = a.w + b.w;
    float s = v0 + v1 + v2 + v3;
#pragma unroll
    for (int o = 16; o > 0; o >>= 1) s += __shfl_xor_sync(0xffffffffu, s, o);
    float mu = s * (1.f / HIDC);
    float d0 = v0 - mu, d1 = v1 - mu, d2 = v2 - mu, d3 = v3 - mu;
    float ss = d0 * d0 + d1 * d1 + d2 * d2 + d3 * d3;
#pragma unroll
    for (int o = 16; o > 0; o >>= 1) ss += __shfl_xor_sync(0xffffffffu, ss, o);
    float rs = rsqrtf(ss * (1.f / HIDC) + EPSLN);
    int col = lane * 4;
    float z0 = fmaxf(d0 * rs * g[col + 0] + bt[col + 0], 0.f);
    float z1 = fmaxf(d1 * rs * g[col + 1] + bt[col + 1], 0.f);
    float z2 = fmaxf(d2 * rs * g[col + 2] + bt[col + 2], 0.f);
    float z3 = fmaxf(d3 * rs * g[col + 3] + bt[col + 3], 0.f);
    float bb = g_betas[li];
    *(float4*)(g_z + base) = make_float4(z0, z1, z2, z3);
    float4 oo = *(float4*)(out + base);
    oo.x += bb * z0; oo.y += bb * z1; oo.z += bb * z2; oo.w += bb * z3;
    *(float4*)(out + base) = oo;
}

__global__ __launch_bounds__(256) void init_acc(float* __restrict__ out) {
    int i = blockIdx.x * blockDim.x + threadIdx.x;
    if (i < NN * HIDC) out[i] = g_betas[0] * g_z[i];
}

// ---------------- host launcher ----------------
extern "C" void kernel_launch(void* const* d_in, const int* in_sizes, int n_in,
                              void* d_out, int out_size) {
    const float* x    = (const float*)d_in[0];
    const void*  ei   = d_in[1];
    const float* Win  = (const float*)d_in[2];
    const float* b_in = (const float*)d_in[3];
    const float* Wq   = (const float*)d_in[4];
    const float* bq   = (const float*)d_in[5];
    const float* Wk   = (const float*)d_in[6];
    const float* bk   = (const float*)d_in[7];
    const float* Wv   = (const float*)d_in[8];
    const float* bv   = (const float*)d_in[9];
    const float* Wsk  = (const float*)d_in[10];
    const float* bsk  = (const float*)d_in[11];
    const float* W1   = (const float*)d_in[12];
    const float* b1   = (const float*)d_in[13];
    const float* W2   = (const float*)d_in[14];
    const float* b2   = (const float*)d_in[15];
    const float* g1   = (const float*)d_in[16];
    const float* bt1  = (const float*)d_in[17];
    const float* g2   = (const float*)d_in[18];
    const float* bt2  = (const float*)d_in[19];
    const float* beta = (const float*)d_in[20];
    float* out = (float*)d_out;

    float *z, *h, *t, *u, *wt;
    cudaGetSymbolAddress((void**)&z, g_z);
    cudaGetSymbolAddress((void**)&h, g_h);
    cudaGetSymbolAddress((void**)&t, g_t);
    cudaGetSymbolAddress((void**)&u, g_u);
    cudaGetSymbolAddress((void**)&wt, g_wt);

    const int GM = (NN + BM - 1) / BM;  // 391

    // captures land on launch index 3 -> representative GEMM there
    sniff_kernel<<<1, 32>>>((const unsigned*)ei);                        // 0
    beta_softmax<<<1, 32>>>(beta);                                       // 1
    convW<<<(TOTW + 255) / 256, 256>>>(Win, Wq, Wk, Wv, Wsk, W1, W2);    // 2
    gemm_tf32<1><<<dim3(GM, 1), 256>>>(x, wt, b_in, z, NN, HIDC, HIDC);  // 3
    gemm_qkvsk<<<dim3(GM, 4), 256>>>(z, wt, bq, bk, bv, bsk, 0);         // 4

    init_acc<<<(NN * HIDC + 255) / 256, 256>>>(out);
    convert_edges<<<(EE + 255) / 256, 256>>>(ei);

    // CSR build (once; needed before first attn)
    k_clear_deg<<<(NN + 255) / 256, 256>>>();
    k_hist<<<(EE + 255) / 256, 256>>>();
    k_chunksum<<<NCHK, CHUNK>>>();
    k_scanchunks<<<1, 32>>>();
    k_rowptr<<<NCHK, CHUNK>>>();
    k_fill<<<(EE + 255) / 256, 256>>>();

    for (int l = 0; l < NLAYERS; l++) {
        if (l > 0)
            gemm_qkvsk<<<dim3(GM, 4), 256>>>(z, wt, bq, bk, bv, bsk, l);

        attn_fused<<<(NN * 32 + 255) / 256, 256>>>();

        ln3_kernel<<<(NN + 7) / 8, 256>>>(g1 + l * HIDC, bt1 + l * HIDC);

        gemm_tf32<2><<<dim3(GM, 2), 256>>>(h, wt + OFF_W1 + (size_t)l * HIDC * FFC,
                                           b1 + l * FFC, t, NN, HIDC, FFC);
        gemm_tf32<0><<<dim3(GM, 1), 256>>>(t, wt + OFF_W2 + (size_t)l * FFC * HIDC,
                                           b2 + l * HIDC, u, NN, FFC, HIDC);

        lnacc_kernel<<<(NN + 7) / 8, 256>>>(g2 + l * HIDC, bt2 + l * HIDC, out, l + 1);
    }
}

// round 11
// speedup vs baseline: 1.0425x; 1.0425x over previous
#include <cuda_runtime.h>
#include <math.h>
#include <stdint.h>

#define NN 50000
#define EE 800000
#define HIDC 128
#define FFC 256
#define NLAYERS 6
#define EPSLN 1e-5f

// ---------------- scratch (device globals; no allocation allowed) ----------------
__device__ float g_z[NN * HIDC];
__device__ float g_q[NN * HIDC];
__device__ float g_k[NN * HIDC];
__device__ float g_v[NN * HIDC];
__device__ float g_sk[NN * HIDC];
__device__ float g_attn[NN * HIDC];
__device__ float g_h[NN * HIDC];
__device__ float g_t[NN * FFC];
__device__ float g_u[NN * HIDC];
__device__ int g_src[EE];
__device__ int g_dst[EE];
__device__ int g_deg[NN];
__device__ int g_rowptr[NN + 1];
__device__ int g_cur[NN];
__device__ int g_csrc[EE];
__device__ int g_csums[128];
__device__ float g_betas[NLAYERS + 2];
__device__ int g_flag[1];

// tf32-preconverted weights, FRAGMENT-MAJOR permuted layout (see convW)
#define OFF_WQ  16384
#define OFF_WK  (OFF_WQ + NLAYERS * HIDC * HIDC)
#define OFF_WV  (OFF_WK + NLAYERS * HIDC * HIDC)
#define OFF_WSK (OFF_WV + NLAYERS * HIDC * HIDC)
#define OFF_W1  (OFF_WSK + NLAYERS * HIDC * HIDC)
#define OFF_W2  (OFF_W1 + NLAYERS * HIDC * FFC)
#define TOTW    (OFF_W2 + NLAYERS * FFC * HIDC)
__device__ float g_wt[TOTW];

#define CHUNK 512
#define NCHK ((NN + CHUNK - 1) / CHUNK)   // 98

// ---------------- helpers ----------------
__device__ __forceinline__ uint32_t f2tf32(float x) {
    uint32_t r;
    asm("cvt.rna.tf32.f32 %0, %1;" : "=r"(r) : "f"(x));
    return r;
}

__device__ __forceinline__ void mma_tf32(float* d, const uint32_t* a, const uint32_t* b) {
    asm volatile(
        "mma.sync.aligned.m16n8k8.row.col.f32.tf32.tf32.f32 "
        "{%0,%1,%2,%3}, {%4,%5,%6,%7}, {%8,%9}, {%0,%1,%2,%3};"
        : "+f"(d[0]), "+f"(d[1]), "+f"(d[2]), "+f"(d[3])
        : "r"(a[0]), "r"(a[1]), "r"(a[2]), "r"(a[3]), "r"(b[0]), "r"(b[1]));
}

__device__ __forceinline__ void cp16(uint32_t saddr, const void* g) {
    asm volatile("cp.async.ca.shared.global [%0], [%1], 16;" ::"r"(saddr), "l"(g));
}
__device__ __forceinline__ void cp_commit() { asm volatile("cp.async.commit_group;"); }
__device__ __forceinline__ void cp_wait0() { asm volatile("cp.async.wait_group 0;"); }

// ---------------- edge index dtype sniff + convert ----------------
__global__ void sniff_kernel(const unsigned* __restrict__ w) {
    if (threadIdx.x == 0 && blockIdx.x == 0) {
        int is64 = 1;
        for (int i = 1; i < 64; i += 2)
            if (w[i] != 0u) { is64 = 0; break; }
        g_flag[0] = is64;
    }
}

__global__ __launch_bounds__(256) void convert_edges(const void* __restrict__ ei) {
    int e = blockIdx.x * blockDim.x + threadIdx.x;
    if (e >= EE) return;
    if (g_flag[0]) {
        const long long* p = (const long long*)ei;
        g_src[e] = (int)p[e];
        g_dst[e] = (int)p[EE + e];
    } else {
        const int* p = (const int*)ei;
        g_src[e] = p[e];
        g_dst[e] = p[EE + e];
    }
}

__global__ void beta_softmax(const float* __restrict__ beta) {
    if (threadIdx.x == 0 && blockIdx.x == 0) {
        float m = -1e30f;
        for (int i = 0; i < NLAYERS + 1; i++) m = fmaxf(m, beta[i]);
        float s = 0.f;
        for (int i = 0; i < NLAYERS + 1; i++) {
            float e = expf(beta[i] - m);
            g_betas[i] = e;
            s += e;
        }
        for (int i = 0; i < NLAYERS + 1; i++) g_betas[i] /= s;
    }
}

// ---------------- weight tf32 convert + fragment-major permute ----------------
// dst float offset within a [K,N] matrix for element (k,n):
//   iter = k>>4; ks=(k>>3)&1; kh=(k>>2)&1; t=k&3; g=n&7; nb8=n>>3
//   off = iter*16*N + (ks*(N/8)+nb8)*64 + (g*4+t)*2 + kh
__device__ __forceinline__ int permW(int k, int n, int N) {
    return (k >> 4) * 16 * N + (((k >> 3) & 1) * (N >> 3) + (n >> 3)) * 64 +
           ((n & 7) * 4 + (k & 3)) * 2 + ((k >> 2) & 1);
}

__global__ __launch_bounds__(256) void convW(
    const float* __restrict__ Win, const float* __restrict__ Wq,
    const float* __restrict__ Wk, const float* __restrict__ Wv,
    const float* __restrict__ Wsk, const float* __restrict__ W1,
    const float* __restrict__ W2) {
    int i = blockIdx.x * blockDim.x + threadIdx.x;
    if (i >= TOTW) return;
    const float* src;
    int base, off, N, matsz;
    if (i < OFF_WQ)       { src = Win; base = 0;       off = i;           N = 128; matsz = HIDC * HIDC; }
    else if (i < OFF_WK)  { src = Wq;  base = OFF_WQ;  off = i - OFF_WQ;  N = 128; matsz = HIDC * HIDC; }
    else if (i < OFF_WV)  { src = Wk;  base = OFF_WK;  off = i - OFF_WK;  N = 128; matsz = HIDC * HIDC; }
    else if (i < OFF_WSK) { src = Wv;  base = OFF_WV;  off = i - OFF_WV;  N = 128; matsz = HIDC * HIDC; }
    else if (i < OFF_W1)  { src = Wsk; base = OFF_WSK; off = i - OFF_WSK; N = 128; matsz = HIDC * HIDC; }
    else if (i < OFF_W2)  { src = W1;  base = OFF_W1;  off = i - OFF_W1;  N = 256; matsz = HIDC * FFC; }
    else                  { src = W2;  base = OFF_W2;  off = i - OFF_W2;  N = 128; matsz = FFC * HIDC; }
    int l = off / matsz;
    int o2 = off - l * matsz;
    int k = o2 / N, n = o2 - k * N;
    float val = src[off];
    g_wt[base + l * matsz + permW(k, n, N)] = __uint_as_float(f2tf32(val));
}

// ---------------- CSR build ----------------
__global__ __launch_bounds__(256) void k_clear_deg() {
    int i = blockIdx.x * blockDim.x + threadIdx.x;
    if (i < NN) g_deg[i] = 0;
}
__global__ __launch_bounds__(256) void k_hist() {
    int e = blockIdx.x * blockDim.x + threadIdx.x;
    if (e < EE) atomicAdd(&g_deg[g_dst[e]], 1);
}
__global__ __launch_bounds__(CHUNK) void k_chunksum() {
    __shared__ int sh[CHUNK];
    int tid = threadIdx.x;
    int i = blockIdx.x * CHUNK + tid;
    sh[tid] = (i < NN) ? g_deg[i] : 0;
    __syncthreads();
    for (int off = CHUNK / 2; off > 0; off >>= 1) {
        if (tid < off) sh[tid] += sh[tid + off];
        __syncthreads();
    }
    if (tid == 0) g_csums[blockIdx.x] = sh[0];
}
__global__ void k_scanchunks() {
    if (threadIdx.x == 0 && blockIdx.x == 0) {
        int run = 0;
        for (int c = 0; c < NCHK; c++) {
            int v = g_csums[c];
            g_csums[c] = run;
            run += v;
        }
        g_rowptr[NN] = run;
    }
}
__global__ __launch_bounds__(CHUNK) void k_rowptr() {
    __shared__ int sh[CHUNK];
    int tid = threadIdx.x;
    int i = blockIdx.x * CHUNK + tid;
    int v = (i < NN) ? g_deg[i] : 0;
    sh[tid] = v;
    __syncthreads();
    for (int off = 1; off < CHUNK; off <<= 1) {
        int t = (tid >= off) ? sh[tid - off] : 0;
        __syncthreads();
        sh[tid] += t;
        __syncthreads();
    }
    if (i < NN) {
        int excl = sh[tid] - v + g_csums[blockIdx.x];
        g_rowptr[i] = excl;
        g_cur[i] = excl;
    }
}
__global__ __launch_bounds__(256) void k_fill() {
    int e = blockIdx.x * blockDim.x + threadIdx.x;
    if (e >= EE) return;
    int slot = atomicAdd(&g_cur[g_dst[e]], 1);
    g_csrc[slot] = g_src[e];
}

// ---------------- TF32 GEMM, fragment-major smem ----------------
// 256 thr, 8 warps (2x4), warp tile 64x32, BK=16.
// A smem: per buffer 8KB: chunk(ks,mb) (2x8) of 512B; within a chunk, 16B slot
//   index is XOR-swizzled: slot' = slot ^ ((slot>>3)&3) to break STS conflicts.
// B smem: per buffer 8KB: chunk(ks,nb8) (2x16) of 256B, lane*8B, words kh
//   (copied contiguous via cp.async from pre-permuted weights).
#define BM 128
#define BN 128
#define BK 16
#define ABUF 2048   // floats per A buffer
#define BBUF 2048   // floats per B buffer

__device__ __forceinline__ int aswz(int slot) {   // 16B-slot swizzle within chunk
    return slot ^ ((slot >> 3) & 3);
}

__device__ __forceinline__ void ldA(
    const float* __restrict__ A, int M, int K, int m0, int kc, int tid,
    float4 ar[2]) {
#pragma unroll
    for (int i = 0; i < 2; i++) {
        int f = tid + i * 256;
        int m = f >> 2, k4 = (f & 3) * 4;
        ar[i] = (m0 + m < M)
                    ? *(const float4*)(A + (size_t)(m0 + m) * K + kc + k4)
                    : make_float4(0.f, 0.f, 0.f, 0.f);
    }
}

// permuted A staging: element (m, k4+j) -> chunk(ks=k4>>3, mb=m>>4),
// slot = (m&7)*4+j (swizzled), word = ((m>>3)&1) + 2*((k4>>2)&1)
__device__ __forceinline__ void stA(float* As, int tid, const float4 ar[2]) {
#pragma unroll
    for (int i = 0; i < 2; i++) {
        int f = tid + i * 256;
        int m = f >> 2, k4 = (f & 3) * 4;
        int ks = k4 >> 3, kh = (k4 >> 2) & 1;
        int g = m & 7, h = (m >> 3) & 1, mb = m >> 4;
        int cb = (ks * 8 + mb) * 128;                  // chunk base (floats)
        int w = h + 2 * kh;
        const float* pv = (const float*)&ar[i];
#pragma unroll
        for (int j = 0; j < 4; j++)
            As[cb + aswz(g * 4 + j) * 4 + w] = __uint_as_float(f2tf32(pv[j]));
    }
}

// B copy: global weights already fragment-major. Per iter the 128-N tile is
// two contiguous 4KB regions (ks=0,1) at gbase + (ks*(N/8)+n0/8)*64 floats.
__device__ __forceinline__ void cpB(uint32_t bs_addr, const float* __restrict__ Bmat,
                                    int N, int n0, int kc, int tid) {
    const float* gbase = Bmat + (size_t)kc * N;
    const float* r0 = gbase + (n0 >> 3) * 64;
    const float* r1 = gbase + ((N >> 3) + (n0 >> 3)) * 64;
#pragma unroll
    for (int i = 0; i < 2; i++) {
        int idx = tid + i * 256;          // 0..511, 16B each
        int soff = idx * 16;              // bytes
        const float* gp = (soff < 4096) ? (r0 + (soff >> 2))
                                        : (r1 + ((soff - 4096) >> 2));
        cp16(bs_addr + soff, gp);
    }
}

template <int ACT>
__device__ __forceinline__ void gemm_core(
    const float* __restrict__ A, const float* __restrict__ Bmat,
    const float* __restrict__ bias, float* __restrict__ C,
    int M, int K, int Nld, int m0, int n0,
    float* As, float* Bs, uint32_t bs_addr) {
    int tid = threadIdx.x;
    int warp = tid >> 5, lane = tid & 31;
    int wm = (warp >> 2) * 64, wn = (warp & 3) * 32;
    int lsw = aswz(lane);   // swizzled 16B slot for A fragment reads

    float acc[4][4][4];
#pragma unroll
    for (int a = 0; a < 4; a++)
#pragma unroll
        for (int b = 0; b < 4; b++)
#pragma unroll
            for (int c = 0; c < 4; c++) acc[a][b][c] = 0.f;

    float4 ar[2];
    ldA(A, M, K, m0, 0, tid, ar);
    cpB(bs_addr, Bmat, Nld, n0, 0, tid);
    stA(As, tid, ar);
    cp_commit();
    cp_wait0();
    __syncthreads();

    int nit = K / BK;
    for (int it = 0; it < nit; it++) {
        int cur = it & 1;
        const float* Ac = As + cur * ABUF;
        const float* Bc = Bs + cur * BBUF;
        if (it + 1 < nit) {
            ldA(A, M, K, m0, (it + 1) * BK, tid, ar);
            cpB(bs_addr + (cur ^ 1) * (BBUF * 4), Bmat, Nld, n0, (it + 1) * BK, tid);
            cp_commit();
        }

#pragma unroll
        for (int ks = 0; ks < 2; ks++) {
            uint4 af[4];
#pragma unroll
            for (int tm = 0; tm < 4; tm++) {
                int mb = (wm >> 4) + tm;
                af[tm] = *(const uint4*)(Ac + (ks * 8 + mb) * 128 + lsw * 4);
            }
            uint2 bf[4];
#pragma unroll
            for (int tn = 0; tn < 4; tn++) {
                int nb = (wn >> 3) + tn;
                bf[tn] = *(const uint2*)(Bc + (ks * 16 + nb) * 64 + lane * 2);
            }
#pragma unroll
            for (int tm = 0; tm < 4; tm++)
#pragma unroll
                for (int tn = 0; tn < 4; tn++)
                    mma_tf32(acc[tm][tn], (const uint32_t*)&af[tm],
                             (const uint32_t*)&bf[tn]);
        }

        if (it + 1 < nit) stA(As + (cur ^ 1) * ABUF, tid, ar);
        cp_wait0();
        __syncthreads();
    }

    // epilogue: c0,c1 row g cols 2t,2t+1 ; c2,c3 row g+8
    int gg = lane >> 2, tt = lane & 3;
#pragma unroll
    for (int tm = 0; tm < 4; tm++) {
        int r0 = m0 + wm + tm * 16 + gg;
        int r1 = r0 + 8;
#pragma unroll
        for (int tn = 0; tn < 4; tn++) {
            int cb = n0 + wn + tn * 8 + 2 * tt;
            float b0 = __ldg(bias + cb);
            float b1 = __ldg(bias + cb + 1);
            float v00 = acc[tm][tn][0] + b0;
            float v01 = acc[tm][tn][1] + b1;
            float v10 = acc[tm][tn][2] + b0;
            float v11 = acc[tm][tn][3] + b1;
            if (ACT == 1) {
                v00 = fmaxf(v00, 0.f); v01 = fmaxf(v01, 0.f);
                v10 = fmaxf(v10, 0.f); v11 = fmaxf(v11, 0.f);
            }
            if (ACT == 2) {
                v00 = 0.5f * v00 * (1.f + erff(v00 * 0.70710678118654752f));
                v01 = 0.5f * v01 * (1.f + erff(v01 * 0.70710678118654752f));
                v10 = 0.5f * v10 * (1.f + erff(v10 * 0.70710678118654752f));
                v11 = 0.5f * v11 * (1.f + erff(v11 * 0.70710678118654752f));
            }
            if (r0 < M) *(float2*)(C + (size_t)r0 * Nld + cb) = make_float2(v00, v01);
            if (r1 < M) *(float2*)(C + (size_t)r1 * Nld + cb) = make_float2(v10, v11);
        }
    }
}

template <int ACT>
__global__ __launch_bounds__(256, 2) void gemm_tf32(
    const float* __restrict__ A, const float* __restrict__ B,
    const float* __restrict__ bias, float* __restrict__ C,
    int M, int K, int Nld) {
    __shared__ __align__(16) float As[2 * ABUF];
    __shared__ __align__(16) float Bs[2 * BBUF];
    uint32_t bs = (uint32_t)__cvta_generic_to_shared(Bs);
    gemm_core<ACT>(A, B, bias, C, M, K, Nld, blockIdx.x * BM, blockIdx.y * BN,
                   As, Bs, bs);
}

// fused Q/K/V/SK projection: grid.y in [0,4) selects operator
__global__ __launch_bounds__(256, 2) void gemm_qkvsk(
    const float* __restrict__ A, const float* __restrict__ wt,
    const float* __restrict__ bq, const float* __restrict__ bk,
    const float* __restrict__ bv, const float* __restrict__ bsk, int l) {
    __shared__ __align__(16) float As[2 * ABUF];
    __shared__ __align__(16) float Bs[2 * BBUF];
    uint32_t bs = (uint32_t)__cvta_generic_to_shared(Bs);
    const float* B;
    const float* bias;
    float* C;
    switch (blockIdx.y) {
        case 0: B = wt + OFF_WQ;  bias = bq;  C = g_q;  break;
        case 1: B = wt + OFF_WK;  bias = bk;  C = g_k;  break;
        case 2: B = wt + OFF_WV;  bias = bv;  C = g_v;  break;
        default: B = wt + OFF_WSK; bias = bsk; C = g_sk; break;
    }
    B += (size_t)l * HIDC * HIDC;
    bias += l * HIDC;
    gemm_core<0>(A, B, bias, C, NN, HIDC, HIDC, blockIdx.x * BM, 0, As, Bs, bs);
}

// ---------------- fused attention: warp/node, online softmax, 2-edge unroll ----
__global__ __launch_bounds__(256) void attn_fused() {
    int node = (blockIdx.x * blockDim.x + threadIdx.x) >> 5;
    if (node >= NN) return;
    int lane = threadIdx.x & 31;
    int beg = g_rowptr[node], end = g_rowptr[node + 1];
    size_t qb = (size_t)node * HIDC + lane * 4;
    float4 qv = *(const float4*)(g_q + qb);
    float m = -INFINITY, l = 0.f;
    float4 acc = make_float4(0.f, 0.f, 0.f, 0.f);
    int e = beg;
    for (; e + 1 < end; e += 2) {
        int s0 = g_csrc[e], s1 = g_csrc[e + 1];
        size_t b0 = (size_t)s0 * HIDC + lane * 4;
        size_t b1 = (size_t)s1 * HIDC + lane * 4;
        float4 k0 = *(const float4*)(g_k + b0);
        float4 k1 = *(const float4*)(g_k + b1);
        float4 v0 = *(const float4*)(g_v + b0);
        float4 v1 = *(const float4*)(g_v + b1);
        float p0 = qv.x * k0.x + qv.y * k0.y + qv.z * k0.z + qv.w * k0.w;
        float p1 = qv.x * k1.x + qv.y * k1.y + qv.z * k1.z + qv.w * k1.w;
        p0 += __shfl_xor_sync(0xffffffffu, p0, 8, 16);
        p1 += __shfl_xor_sync(0xffffffffu, p1, 8, 16);
        p0 += __shfl_xor_sync(0xffffffffu, p0, 4, 16);
        p1 += __shfl_xor_sync(0xffffffffu, p1, 4, 16);
        p0 += __shfl_xor_sync(0xffffffffu, p0, 2, 16);
        p1 += __shfl_xor_sync(0xffffffffu, p1, 2, 16);
        p0 += __shfl_xor_sync(0xffffffffu, p0, 1, 16);
        p1 += __shfl_xor_sync(0xffffffffu, p1, 1, 16);
        float sc0 = p0 * 0.125f;
        float sc1 = p1 * 0.125f;
        float mn = fmaxf(m, fmaxf(sc0, sc1));
        float scale = __expf(m - mn);
        float w0 = __expf(sc0 - mn);
        float w1 = __expf(sc1 - mn);
        l = l * scale + w0 + w1;
        acc.x = acc.x * scale + w0 * v0.x + w1 * v1.x;
        acc.y = acc.y * scale + w0 * v0.y + w1 * v1.y;
        acc.z = acc.z * scale + w0 * v0.z + w1 * v1.z;
        acc.w = acc.w * scale + w0 * v0.w + w1 * v1.w;
        m = mn;
    }
    if (e < end) {
        int s = g_csrc[e];
        size_t sb = (size_t)s * HIDC + lane * 4;
        float4 kv = *(const float4*)(g_k + sb);
        float4 vv = *(const float4*)(g_v + sb);
        float p = qv.x * kv.x + qv.y * kv.y + qv.z * kv.z + qv.w * kv.w;
        p += __shfl_xor_sync(0xffffffffu, p, 8, 16);
        p += __shfl_xor_sync(0xffffffffu, p, 4, 16);
        p += __shfl_xor_sync(0xffffffffu, p, 2, 16);
        p += __shfl_xor_sync(0xffffffffu, p, 1, 16);
        float sc = p * 0.125f;
        float mn = fmaxf(m, sc);
        float scale = __expf(m - mn);
        float w = __expf(sc - mn);
        l = l * scale + w;
        acc.x = acc.x * scale + w * vv.x;
        acc.y = acc.y * scale + w * vv.y;
        acc.z = acc.z * scale + w * vv.z;
        acc.w = acc.w * scale + w * vv.w;
    }
    float inv = (l > 0.f) ? 1.f / l : 0.f;
    acc.x *= inv; acc.y *= inv; acc.z *= inv; acc.w *= inv;
    *(float4*)(g_attn + qb) = acc;
}

// ---------------- layernorm kernels (warp per row, 128 cols) ----------------
__global__ __launch_bounds__(256) void ln3_kernel(
    const float* __restrict__ g, const float* __restrict__ bt) {
    int row = (blockIdx.x * blockDim.x + threadIdx.x) >> 5;
    if (row >= NN) return;
    int lane = threadIdx.x & 31;
    size_t base = (size_t)row * HIDC + lane * 4;
    float4 a = *(const float4*)(g_z + base);
    float4 b = *(const float4*)(g_attn + base);
    float4 c = *(const float4*)(g_sk + base);
    float v0 = a.x + b.x + c.x, v1 = a.y + b.y + c.y;
    float v2 = a.z + b.z + c.z, v3 = a.w + b.w + c.w;
    float s = v0 + v1 + v2 + v3;
#pragma unroll
    for (int o = 16; o > 0; o >>= 1) s += __shfl_xor_sync(0xffffffffu, s, o);
    float mu = s * (1.f / HIDC);
    float d0 = v0 - mu, d1 = v1 - mu, d2 = v2 - mu, d3 = v3 - mu;
    float ss = d0 * d0 + d1 * d1 + d2 * d2 + d3 * d3;
#pragma unroll
    for (int o = 16; o > 0; o >>= 1) ss += __shfl_xor_sync(0xffffffffu, ss, o);
    float rs = rsqrtf(ss * (1.f / HIDC) + EPSLN);
    int col = lane * 4;
    float4 o4;
    o4.x = d0 * rs * g[col + 0] + bt[col + 0];
    o4.y = d1 * rs * g[col + 1] + bt[col + 1];
    o4.z = d2 * rs * g[col + 2] + bt[col + 2];
    o4.w = d3 * rs * g[col + 3] + bt[col + 3];
    *(float4*)(g_h + base) = o4;
}

// z = relu(LN(h+u)); out += betas[li]*z
__global__ __launch_bounds__(256) void lnacc_kernel(
    const float* __restrict__ g, const float* __restrict__ bt,
    float* __restrict__ out, int li) {
    int row = (blockIdx.x * blockDim.x + threadIdx.x) >> 5;
    if (row >= NN) return;
    int lane = threadIdx.x & 31;
    size_t base = (size_t)row * HIDC + lane * 4;
    float4 a = *(const float4*)(g_h + base);
    float4 b = *(const float4*)(g_u + base);
    float v0 = a.x + b.x, v1 = a.y + b.y, v2 = a.z + b.z, v3 = a.w + b.w;
    float s = v0 + v1 + v2 + v3;
#pragma unroll
    for (int o = 16; o > 0; o >>= 1) s += __shfl_xor_sync(0xffffffffu, s, o);
    float mu = s * (1.f / HIDC);
    float d0 = v0 - mu, d1 = v1 - mu, d2 = v2 - mu, d3 = v3 - mu;
    float ss = d0 * d0 + d1 * d1 + d2 * d2 + d3 * d3;
#pragma unroll
    for (int o = 16; o > 0; o >>= 1) ss += __shfl_xor_sync(0xffffffffu, ss, o);
    float rs = rsqrtf(ss * (1.f / HIDC) + EPSLN);
    int col = lane * 4;
    float z0 = fmaxf(d0 * rs * g[col + 0] + bt[col + 0], 0.f);
    float z1 = fmaxf(d1 * rs * g[col + 1] + bt[col + 1], 0.f);
    float z2 = fmaxf(d2 * rs * g[col + 2] + bt[col + 2], 0.f);
    float z3 = fmaxf(d3 * rs * g[col + 3] + bt[col + 3], 0.f);
    float bb = g_betas[li];
    *(float4*)(g_z + base) = make_float4(z0, z1, z2, z3);
    float4 oo = *(float4*)(out + base);
    oo.x += bb * z0; oo.y += bb * z1; oo.z += bb * z2; oo.w += bb * z3;
    *(float4*)(out + base) = oo;
}

__global__ __launch_bounds__(256) void init_acc(float* __restrict__ out) {
    int i = blockIdx.x * blockDim.x + threadIdx.x;
    if (i < NN * HIDC) out[i] = g_betas[0] * g_z[i];
}

// ---------------- host launcher ----------------
extern "C" void kernel_launch(void* const* d_in, const int* in_sizes, int n_in,
                              void* d_out, int out_size) {
    const float* x    = (const float*)d_in[0];
    const void*  ei   = d_in[1];
    const float* Win  = (const float*)d_in[2];
    const float* b_in = (const float*)d_in[3];
    const float* Wq   = (const float*)d_in[4];
    const float* bq   = (const float*)d_in[5];
    const float* Wk   = (const float*)d_in[6];
    const float* bk   = (const float*)d_in[7];
    const float* Wv   = (const float*)d_in[8];
    const float* bv   = (const float*)d_in[9];
    const float* Wsk  = (const float*)d_in[10];
    const float* bsk  = (const float*)d_in[11];
    const float* W1   = (const float*)d_in[12];
    const float* b1   = (const float*)d_in[13];
    const float* W2   = (const float*)d_in[14];
    const float* b2   = (const float*)d_in[15];
    const float* g1   = (const float*)d_in[16];
    const float* bt1  = (const float*)d_in[17];
    const float* g2   = (const float*)d_in[18];
    const float* bt2  = (const float*)d_in[19];
    const float* beta = (const float*)d_in[20];
    float* out = (float*)d_out;

    float *z, *h, *t, *u, *wt;
    cudaGetSymbolAddress((void**)&z, g_z);
    cudaGetSymbolAddress((void**)&h, g_h);
    cudaGetSymbolAddress((void**)&t, g_t);
    cudaGetSymbolAddress((void**)&u, g_u);
    cudaGetSymbolAddress((void**)&wt, g_wt);

    const int GM = (NN + BM - 1) / BM;  // 391

    // captures land on launch index 3 -> representative GEMM there
    sniff_kernel<<<1, 32>>>((const unsigned*)ei);                        // 0
    beta_softmax<<<1, 32>>>(beta);                                       // 1
    convW<<<(TOTW + 255) / 256, 256>>>(Win, Wq, Wk, Wv, Wsk, W1, W2);    // 2
    gemm_tf32<1><<<dim3(GM, 1), 256>>>(x, wt, b_in, z, NN, HIDC, HIDC);  // 3
    gemm_qkvsk<<<dim3(GM, 4), 256>>>(z, wt, bq, bk, bv, bsk, 0);         // 4

    init_acc<<<(NN * HIDC + 255) / 256, 256>>>(out);
    convert_edges<<<(EE + 255) / 256, 256>>>(ei);

    // CSR build (once; needed before first attn)
    k_clear_deg<<<(NN + 255) / 256, 256>>>();
    k_hist<<<(EE + 255) / 256, 256>>>();
    k_chunksum<<<NCHK, CHUNK>>>();
    k_scanchunks<<<1, 32>>>();
    k_rowptr<<<NCHK, CHUNK>>>();
    k_fill<<<(EE + 255) / 256, 256>>>();

    for (int l = 0; l < NLAYERS; l++) {
        if (l > 0)
            gemm_qkvsk<<<dim3(GM, 4), 256>>>(z, wt, bq, bk, bv, bsk, l);

        attn_fused<<<(NN * 32 + 255) / 256, 256>>>();

        ln3_kernel<<<(NN + 7) / 8, 256>>>(g1 + l * HIDC, bt1 + l * HIDC);

        gemm_tf32<2><<<dim3(GM, 2), 256>>>(h, wt + OFF_W1 + (size_t)l * HIDC * FFC,
                                           b1 + l * FFC, t, NN, HIDC, FFC);
        gemm_tf32<0><<<dim3(GM, 1), 256>>>(t, wt + OFF_W2 + (size_t)l * FFC * HIDC,
                                           b2 + l * HIDC, u, NN, FFC, HIDC);

        lnacc_kernel<<<(NN + 7) / 8, 256>>>(g2 + l * HIDC, bt2 + l * HIDC, out, l + 1);
    }
}

// round 12
// speedup vs baseline: 1.1793x; 1.1312x over previous
#include <cuda_runtime.h>
#include <cuda_fp16.h>
#include <math.h>
#include <stdint.h>

#define NN 50000
#define EE 800000
#define HIDC 128
#define FFC 256
#define NLAYERS 6
#define EPSLN 1e-5f

// ---------------- scratch (device globals; no allocation allowed) ----------------
__device__ float g_z[NN * HIDC];
__device__ float g_q[NN * HIDC];
__device__ float g_k[NN * HIDC];
__device__ float g_v[NN * HIDC];
__device__ float g_sk[NN * HIDC];
__device__ float g_attn[NN * HIDC];
__device__ float g_h[NN * HIDC];
__device__ float g_t[NN * FFC];
__device__ float g_u[NN * HIDC];
__device__ int g_src[EE];
__device__ int g_dst[EE];
__device__ int g_deg[NN];
__device__ int g_rowptr[NN + 1];
__device__ int g_cur[NN];
__device__ int g_csrc[EE];
__device__ int g_csums[128];
__device__ float g_betas[NLAYERS + 2];
__device__ int g_flag[1];

// fp16-preconverted weights, FRAGMENT-MAJOR (m16n8k16) layout; element offsets
#define OFF_WQ  16384
#define OFF_WK  (OFF_WQ + NLAYERS * HIDC * HIDC)
#define OFF_WV  (OFF_WK + NLAYERS * HIDC * HIDC)
#define OFF_WSK (OFF_WV + NLAYERS * HIDC * HIDC)
#define OFF_W1  (OFF_WSK + NLAYERS * HIDC * HIDC)
#define OFF_W2  (OFF_W1 + NLAYERS * HIDC * FFC)
#define TOTW    (OFF_W2 + NLAYERS * FFC * HIDC)
__device__ __half g_wt[TOTW];

#define CHUNK 512
#define NCHK ((NN + CHUNK - 1) / CHUNK)   // 98

// ---------------- helpers ----------------
__device__ __forceinline__ void mma_f16(float* d, const uint32_t* a, const uint32_t* b) {
    asm volatile(
        "mma.sync.aligned.m16n8k16.row.col.f32.f16.f16.f32 "
        "{%0,%1,%2,%3}, {%4,%5,%6,%7}, {%8,%9}, {%0,%1,%2,%3};"
        : "+f"(d[0]), "+f"(d[1]), "+f"(d[2]), "+f"(d[3])
        : "r"(a[0]), "r"(a[1]), "r"(a[2]), "r"(a[3]), "r"(b[0]), "r"(b[1]));
}

__device__ __forceinline__ void cp16(uint32_t saddr, const void* g) {
    asm volatile("cp.async.ca.shared.global [%0], [%1], 16;" ::"r"(saddr), "l"(g));
}
__device__ __forceinline__ void cp_commit() { asm volatile("cp.async.commit_group;"); }
__device__ __forceinline__ void cp_wait0() { asm volatile("cp.async.wait_group 0;"); }

// ---------------- edge index dtype sniff + convert ----------------
__global__ void sniff_kernel(const unsigned* __restrict__ w) {
    if (threadIdx.x == 0 && blockIdx.x == 0) {
        int is64 = 1;
        for (int i = 1; i < 64; i += 2)
            if (w[i] != 0u) { is64 = 0; break; }
        g_flag[0] = is64;
    }
}

__global__ __launch_bounds__(256) void convert_edges(const void* __restrict__ ei) {
    int e = blockIdx.x * blockDim.x + threadIdx.x;
    if (e >= EE) return;
    if (g_flag[0]) {
        const long long* p = (const long long*)ei;
        g_src[e] = (int)p[e];
        g_dst[e] = (int)p[EE + e];
    } else {
        const int* p = (const int*)ei;
        g_src[e] = p[e];
        g_dst[e] = p[EE + e];
    }
}

__global__ void beta_softmax(const float* __restrict__ beta) {
    if (threadIdx.x == 0 && blockIdx.x == 0) {
        float m = -1e30f;
        for (int i = 0; i < NLAYERS + 1; i++) m = fmaxf(m, beta[i]);
        float s = 0.f;
        for (int i = 0; i < NLAYERS + 1; i++) {
            float e = expf(beta[i] - m);
            g_betas[i] = e;
            s += e;
        }
        for (int i = 0; i < NLAYERS + 1; i++) g_betas[i] /= s;
    }
}

// ---------------- weight fp16 convert + m16n8k16 fragment-major permute -------
// dst fp16 offset within a [K,N] matrix for element (k,n):
//   iter=k>>4; lane=(n&7)*4+((k&7)>>1); reg=(k>>3)&1; u=k&1
//   off = iter*16*N + (n>>3)*128 + lane*4 + reg*2 + u
__device__ __forceinline__ int permW16(int k, int n, int N) {
    return (k >> 4) * 16 * N + (n >> 3) * 128 +
           ((n & 7) * 4 + ((k & 7) >> 1)) * 4 + ((k >> 3) & 1) * 2 + (k & 1);
}

__global__ __launch_bounds__(256) void convW(
    const float* __restrict__ Win, const float* __restrict__ Wq,
    const float* __restrict__ Wk, const float* __restrict__ Wv,
    const float* __restrict__ Wsk, const float* __restrict__ W1,
    const float* __restrict__ W2) {
    int i = blockIdx.x * blockDim.x + threadIdx.x;
    if (i >= TOTW) return;
    const float* src;
    int base, off, N, matsz;
    if (i < OFF_WQ)       { src = Win; base = 0;       off = i;           N = 128; matsz = HIDC * HIDC; }
    else if (i < OFF_WK)  { src = Wq;  base = OFF_WQ;  off = i - OFF_WQ;  N = 128; matsz = HIDC * HIDC; }
    else if (i < OFF_WV)  { src = Wk;  base = OFF_WK;  off = i - OFF_WK;  N = 128; matsz = HIDC * HIDC; }
    else if (i < OFF_WSK) { src = Wv;  base = OFF_WV;  off = i - OFF_WV;  N = 128; matsz = HIDC * HIDC; }
    else if (i < OFF_W1)  { src = Wsk; base = OFF_WSK; off = i - OFF_WSK; N = 128; matsz = HIDC * HIDC; }
    else if (i < OFF_W2)  { src = W1;  base = OFF_W1;  off = i - OFF_W1;  N = 256; matsz = HIDC * FFC; }
    else                  { src = W2;  base = OFF_W2;  off = i - OFF_W2;  N = 128; matsz = FFC * HIDC; }
    int l = off / matsz;
    int o2 = off - l * matsz;
    int k = o2 / N, n = o2 - k * N;
    g_wt[base + l * matsz + permW16(k, n, N)] = __float2half_rn(src[off]);
}

// ---------------- CSR build ----------------
__global__ __launch_bounds__(256) void k_clear_deg() {
    int i = blockIdx.x * blockDim.x + threadIdx.x;
    if (i < NN) g_deg[i] = 0;
}
__global__ __launch_bounds__(256) void k_hist() {
    int e = blockIdx.x * blockDim.x + threadIdx.x;
    if (e < EE) atomicAdd(&g_deg[g_dst[e]], 1);
}
__global__ __launch_bounds__(CHUNK) void k_chunksum() {
    __shared__ int sh[CHUNK];
    int tid = threadIdx.x;
    int i = blockIdx.x * CHUNK + tid;
    sh[tid] = (i < NN) ? g_deg[i] : 0;
    __syncthreads();
    for (int off = CHUNK / 2; off > 0; off >>= 1) {
        if (tid < off) sh[tid] += sh[tid + off];
        __syncthreads();
    }
    if (tid == 0) g_csums[blockIdx.x] = sh[0];
}
__global__ void k_scanchunks() {
    if (threadIdx.x == 0 && blockIdx.x == 0) {
        int run = 0;
        for (int c = 0; c < NCHK; c++) {
            int v = g_csums[c];
            g_csums[c] = run;
            run += v;
        }
        g_rowptr[NN] = run;
    }
}
__global__ __launch_bounds__(CHUNK) void k_rowptr() {
    __shared__ int sh[CHUNK];
    int tid = threadIdx.x;
    int i = blockIdx.x * CHUNK + tid;
    int v = (i < NN) ? g_deg[i] : 0;
    sh[tid] = v;
    __syncthreads();
    for (int off = 1; off < CHUNK; off <<= 1) {
        int t = (tid >= off) ? sh[tid - off] : 0;
        __syncthreads();
        sh[tid] += t;
        __syncthreads();
    }
    if (i < NN) {
        int excl = sh[tid] - v + g_csums[blockIdx.x];
        g_rowptr[i] = excl;
        g_cur[i] = excl;
    }
}
__global__ __launch_bounds__(256) void k_fill() {
    int e = blockIdx.x * blockDim.x + threadIdx.x;
    if (e >= EE) return;
    int slot = atomicAdd(&g_cur[g_dst[e]], 1);
    g_csrc[slot] = g_src[e];
}

// ---------------- FP16 GEMM (m16n8k16), fragment-major smem ----------------
// 256 thr, 8 warps (2x4), warp tile 64x32, BK=16.
// A smem buffer 4KB: 8 chunks (m16) x 512B; slot=lane (16B), regs h+2kb.
// B smem buffer 4KB: 16 chunks (n8) x 256B; slot=lane (8B), regs (k>>3)&1.
#define BM 128
#define BN 128
#define BK 16
#define ABUF 2048   // halves per A buffer
#define BBUF 2048   // halves per B buffer

__device__ __forceinline__ void ldA(
    const float* __restrict__ A, int M, int K, int m0, int kc, int tid,
    float4 ar[2]) {
#pragma unroll
    for (int i = 0; i < 2; i++) {
        int f = tid + i * 256;
        int m = f >> 2, k4 = (f & 3) * 4;
        ar[i] = (m0 + m < M)
                    ? *(const float4*)(A + (size_t)(m0 + m) * K + kc + k4)
                    : make_float4(0.f, 0.f, 0.f, 0.f);
    }
}

// A staging: thread f owns row m=f>>2, k4=(f&3)*4 (4 fp32 -> 2 half2 words).
// chunk mb=m>>4 (128 half2); slot lane=(m&7)*4 + ((k4&7)>>1) (+1 for 2nd pair);
// reg = ((m>>3)&1) + 2*((k4>>3)&1)
__device__ __forceinline__ void stA(__half2* As2, int tid, const float4 ar[2]) {
#pragma unroll
    for (int i = 0; i < 2; i++) {
        int f = tid + i * 256;
        int m = f >> 2, k4 = (f & 3) * 4;
        int g = m & 7, h = (m >> 3) & 1, mb = m >> 4;
        int t = (k4 & 7) >> 1;             // 0 or 2
        int kb = (k4 >> 3) & 1;
        int reg = h + 2 * kb;
        int cb = mb * 128;                 // chunk base in half2
        __half2 p0 = __floats2half2_rn(ar[i].x, ar[i].y);
        __half2 p1 = __floats2half2_rn(ar[i].z, ar[i].w);
        As2[cb + (g * 4 + t) * 4 + reg] = p0;
        As2[cb + (g * 4 + t + 1) * 4 + reg] = p1;
    }
}

// B copy: weights pre-permuted; per iter the needed 128-N tile is one
// contiguous 4KB region at (kc*N + (n0>>3)*128) halves.
__device__ __forceinline__ void cpB(uint32_t bs_addr, const __half* __restrict__ Bmat,
                                    int N, int n0, int kc, int tid) {
    const __half* gp = Bmat + (size_t)kc * N + (n0 >> 3) * 128;
    cp16(bs_addr + tid * 16, gp + tid * 8);
}

template <int ACT>
__device__ __forceinline__ void gemm_core(
    const float* __restrict__ A, const __half* __restrict__ Bmat,
    const float* __restrict__ bias, float* __restrict__ C,
    int M, int K, int Nld, int m0, int n0,
    __half* As, __half* Bs, uint32_t bs_addr) {
    int tid = threadIdx.x;
    int warp = tid >> 5, lane = tid & 31;
    int wm = (warp >> 2) * 64, wn = (warp & 3) * 32;
    __half2* As2 = (__half2*)As;

    float acc[4][4][4];
#pragma unroll
    for (int a = 0; a < 4; a++)
#pragma unroll
        for (int b = 0; b < 4; b++)
#pragma unroll
            for (int c = 0; c < 4; c++) acc[a][b][c] = 0.f;

    float4 ar[2];
    ldA(A, M, K, m0, 0, tid, ar);
    cpB(bs_addr, Bmat, Nld, n0, 0, tid);
    stA(As2, tid, ar);
    cp_commit();
    cp_wait0();
    __syncthreads();

    int nit = K / BK;
    for (int it = 0; it < nit; it++) {
        int cur = it & 1;
        const __half* Ac = As + cur * ABUF;
        const __half* Bc = Bs + cur * BBUF;
        if (it + 1 < nit) {
            ldA(A, M, K, m0, (it + 1) * BK, tid, ar);
            cpB(bs_addr + (cur ^ 1) * (BBUF * 2), Bmat, Nld, n0, (it + 1) * BK, tid);
            cp_commit();
        }

        uint4 af[4];
#pragma unroll
        for (int tm = 0; tm < 4; tm++) {
            int mb = (wm >> 4) + tm;
            af[tm] = *(const uint4*)(Ac + mb * 256 + lane * 8);
        }
        uint2 bf[4];
#pragma unroll
        for (int tn = 0; tn < 4; tn++) {
            int nb = (wn >> 3) + tn;
            bf[tn] = *(const uint2*)(Bc + nb * 128 + lane * 4);
        }
#pragma unroll
        for (int tm = 0; tm < 4; tm++)
#pragma unroll
            for (int tn = 0; tn < 4; tn++)
                mma_f16(acc[tm][tn], (const uint32_t*)&af[tm],
                        (const uint32_t*)&bf[tn]);

        if (it + 1 < nit) stA((__half2*)(As + (cur ^ 1) * ABUF), tid, ar);
        cp_wait0();
        __syncthreads();
    }

    // epilogue: c0,c1 row g cols 2t,2t+1 ; c2,c3 row g+8
    int gg = lane >> 2, tt = lane & 3;
#pragma unroll
    for (int tm = 0; tm < 4; tm++) {
        int r0 = m0 + wm + tm * 16 + gg;
        int r1 = r0 + 8;
#pragma unroll
        for (int tn = 0; tn < 4; tn++) {
            int cb = n0 + wn + tn * 8 + 2 * tt;
            float b0 = __ldg(bias + cb);
            float b1 = __ldg(bias + cb + 1);
            float v00 = acc[tm][tn][0] + b0;
            float v01 = acc[tm][tn][1] + b1;
            float v10 = acc[tm][tn][2] + b0;
            float v11 = acc[tm][tn][3] + b1;
            if (ACT == 1) {
                v00 = fmaxf(v00, 0.f); v01 = fmaxf(v01, 0.f);
                v10 = fmaxf(v10, 0.f); v11 = fmaxf(v11, 0.f);
            }
            if (ACT == 2) {
                v00 = 0.5f * v00 * (1.f + erff(v00 * 0.70710678118654752f));
                v01 = 0.5f * v01 * (1.f + erff(v01 * 0.70710678118654752f));
                v10 = 0.5f * v10 * (1.f + erff(v10 * 0.70710678118654752f));
                v11 = 0.5f * v11 * (1.f + erff(v11 * 0.70710678118654752f));
            }
            if (r0 < M) *(float2*)(C + (size_t)r0 * Nld + cb) = make_float2(v00, v01);
            if (r1 < M) *(float2*)(C + (size_t)r1 * Nld + cb) = make_float2(v10, v11);
        }
    }
}

template <int ACT>
__global__ __launch_bounds__(256, 2) void gemm_f16(
    const float* __restrict__ A, const __half* __restrict__ B,
    const float* __restrict__ bias, float* __restrict__ C,
    int M, int K, int Nld) {
    __shared__ __align__(16) __half As[2 * ABUF];
    __shared__ __align__(16) __half Bs[2 * BBUF];
    uint32_t bs = (uint32_t)__cvta_generic_to_shared(Bs);
    gemm_core<ACT>(A, B, bias, C, M, K, Nld, blockIdx.x * BM, blockIdx.y * BN,
                   As, Bs, bs);
}

// fused Q/K/V/SK projection: grid.y in [0,4) selects operator
__global__ __launch_bounds__(256, 2) void gemm_qkvsk(
    const float* __restrict__ A, const __half* __restrict__ wt,
    const float* __restrict__ bq, const float* __restrict__ bk,
    const float* __restrict__ bv, const float* __restrict__ bsk, int l) {
    __shared__ __align__(16) __half As[2 * ABUF];
    __shared__ __align__(16) __half Bs[2 * BBUF];
    uint32_t bs = (uint32_t)__cvta_generic_to_shared(Bs);
    const __half* B;
    const float* bias;
    float* C;
    switch (blockIdx.y) {
        case 0: B = wt + OFF_WQ;  bias = bq;  C = g_q;  break;
        case 1: B = wt + OFF_WK;  bias = bk;  C = g_k;  break;
        case 2: B = wt + OFF_WV;  bias = bv;  C = g_v;  break;
        default: B = wt + OFF_WSK; bias = bsk; C = g_sk; break;
    }
    B += (size_t)l * HIDC * HIDC;
    bias += l * HIDC;
    gemm_core<0>(A, B, bias, C, NN, HIDC, HIDC, blockIdx.x * BM, 0, As, Bs, bs);
}

// ---------------- fused attention: warp/node, online softmax, 2-edge unroll ----
__global__ __launch_bounds__(256) void attn_fused() {
    int node = (blockIdx.x * blockDim.x + threadIdx.x) >> 5;
    if (node >= NN) return;
    int lane = threadIdx.x & 31;
    int beg = g_rowptr[node], end = g_rowptr[node + 1];
    size_t qb = (size_t)node * HIDC + lane * 4;
    float4 qv = *(const float4*)(g_q + qb);
    float m = -INFINITY, l = 0.f;
    float4 acc = make_float4(0.f, 0.f, 0.f, 0.f);
    int e = beg;
    for (; e + 1 < end; e += 2) {
        int s0 = g_csrc[e], s1 = g_csrc[e + 1];
        size_t b0 = (size_t)s0 * HIDC + lane * 4;
        size_t b1 = (size_t)s1 * HIDC + lane * 4;
        float4 k0 = *(const float4*)(g_k + b0);
        float4 k1 = *(const float4*)(g_k + b1);
        float4 v0 = *(const float4*)(g_v + b0);
        float4 v1 = *(const float4*)(g_v + b1);
        float p0 = qv.x * k0.x + qv.y * k0.y + qv.z * k0.z + qv.w * k0.w;
        float p1 = qv.x * k1.x + qv.y * k1.y + qv.z * k1.z + qv.w * k1.w;
        p0 += __shfl_xor_sync(0xffffffffu, p0, 8, 16);
        p1 += __shfl_xor_sync(0xffffffffu, p1, 8, 16);
        p0 += __shfl_xor_sync(0xffffffffu, p0, 4, 16);
        p1 += __shfl_xor_sync(0xffffffffu, p1, 4, 16);
        p0 += __shfl_xor_sync(0xffffffffu, p0, 2, 16);
        p1 += __shfl_xor_sync(0xffffffffu, p1, 2, 16);
        p0 += __shfl_xor_sync(0xffffffffu, p0, 1, 16);
        p1 += __shfl_xor_sync(0xffffffffu, p1, 1, 16);
        float sc0 = p0 * 0.125f;
        float sc1 = p1 * 0.125f;
        float mn = fmaxf(m, fmaxf(sc0, sc1));
        float scale = __expf(m - mn);
        float w0 = __expf(sc0 - mn);
        float w1 = __expf(sc1 - mn);
        l = l * scale + w0 + w1;
        acc.x = acc.x * scale + w0 * v0.x + w1 * v1.x;
        acc.y = acc.y * scale + w0 * v0.y + w1 * v1.y;
        acc.z = acc.z * scale + w0 * v0.z + w1 * v1.z;
        acc.w = acc.w * scale + w0 * v0.w + w1 * v1.w;
        m = mn;
    }
    if (e < end) {
        int s = g_csrc[e];
        size_t sb = (size_t)s * HIDC + lane * 4;
        float4 kv = *(const float4*)(g_k + sb);
        float4 vv = *(const float4*)(g_v + sb);
        float p = qv.x * kv.x + qv.y * kv.y + qv.z * kv.z + qv.w * kv.w;
        p += __shfl_xor_sync(0xffffffffu, p, 8, 16);
        p += __shfl_xor_sync(0xffffffffu, p, 4, 16);
        p += __shfl_xor_sync(0xffffffffu, p, 2, 16);
        p += __shfl_xor_sync(0xffffffffu, p, 1, 16);
        float sc = p * 0.125f;
        float mn = fmaxf(m, sc);
        float scale = __expf(m - mn);
        float w = __expf(sc - mn);
        l = l * scale + w;
        acc.x = acc.x * scale + w * vv.x;
        acc.y = acc.y * scale + w * vv.y;
        acc.z = acc.z * scale + w * vv.z;
        acc.w = acc.w * scale + w * vv.w;
    }
    float inv = (l > 0.f) ? 1.f / l : 0.f;
    acc.x *= inv; acc.y *= inv; acc.z *= inv; acc.w *= inv;
    *(float4*)(g_attn + qb) = acc;
}

// ---------------- layernorm kernels (warp per row, 128 cols) ----------------
__global__ __launch_bounds__(256) void ln3_kernel(
    const float* __restrict__ g, const float* __restrict__ bt) {
    int row = (blockIdx.x * blockDim.x + threadIdx.x) >> 5;
    if (row >= NN) return;
    int lane = threadIdx.x & 31;
    size_t base = (size_t)row * HIDC + lane * 4;
    float4 a = *(const float4*)(g_z + base);
    float4 b = *(const float4*)(g_attn + base);
    float4 c = *(const float4*)(g_sk + base);
    float v0 = a.x + b.x + c.x, v1 = a.y + b.y + c.y;
    float v2 = a.z + b.z + c.z, v3 = a.w + b.w + c.w;
    float s = v0 + v1 + v2 + v3;
#pragma unroll
    for (int o = 16; o > 0; o >>= 1) s += __shfl_xor_sync(0xffffffffu, s, o);
    float mu = s * (1.f / HIDC);
    float d0 = v0 - mu, d1 = v1 - mu, d2 = v2 - mu, d3 = v3 - mu;
    float ss = d0 * d0 + d1 * d1 + d2 * d2 + d3 * d3;
#pragma unroll
    for (int o = 16; o > 0; o >>= 1) ss += __shfl_xor_sync(0xffffffffu, ss, o);
    float rs = rsqrtf(ss * (1.f / HIDC) + EPSLN);
    int col = lane * 4;
    float4 o4;
    o4.x = d0 * rs * g[col + 0] + bt[col + 0];
    o4.y = d1 * rs * g[col + 1] + bt[col + 1];
    o4.z = d2 * rs * g[col + 2] + bt[col + 2];
    o4.w = d3 * rs * g[col + 3] + bt[col + 3];
    *(float4*)(g_h + base) = o4;
}

// z = relu(LN(h+u)); out += betas[li]*z
__global__ __launch_bounds__(256) void lnacc_kernel(
    const float* __restrict__ g, const float* __restrict__ bt,
    float* __restrict__ out, int li) {
    int row = (blockIdx.x * blockDim.x + threadIdx.x) >> 5;
    if (row >= NN) return;
    int lane = threadIdx.x & 31;
    size_t base = (size_t)row * HIDC + lane * 4;
    float4 a = *(const float4*)(g_h + base);
    float4 b = *(const float4*)(g_u + base);
    float v0 = a.x + b.x, v1 = a.y + b.y, v2 = a.z + b.z, v3 = a.w + b.w;
    float s = v0 + v1 + v2 + v3;
#pragma unroll
    for (int o = 16; o > 0; o >>= 1) s += __shfl_xor_sync(0xffffffffu, s, o);
    float mu = s * (1.f / HIDC);
    float d0 = v0 - mu, d1 = v1 - mu, d2 = v2 - mu, d3 = v3 - mu;
    float ss = d0 * d0 + d1 * d1 + d2 * d2 + d3 * d3;
#pragma unroll
    for (int o = 16; o > 0; o >>= 1) ss += __shfl_xor_sync(0xffffffffu, ss, o);
    float rs = rsqrtf(ss * (1.f / HIDC) + EPSLN);
    int col = lane * 4;
    float z0 = fmaxf(d0 * rs * g[col + 0] + bt[col + 0], 0.f);
    float z1 = fmaxf(d1 * rs * g[col + 1] + bt[col + 1], 0.f);
    float z2 = fmaxf(d2 * rs * g[col + 2] + bt[col + 2], 0.f);
    float z3 = fmaxf(d3 * rs * g[col + 3] + bt[col + 3], 0.f);
    float bb = g_betas[li];
    *(float4*)(g_z + base) = make_float4(z0, z1, z2, z3);
    float4 oo = *(float4*)(out + base);
    oo.x += bb * z0; oo.y += bb * z1; oo.z += bb * z2; oo.w += bb * z3;
    *(float4*)(out + base) = oo;
}

__global__ __launch_bounds__(256) void init_acc(float* __restrict__ out) {
    int i = blockIdx.x * blockDim.x + threadIdx.x;
    if (i < NN * HIDC) out[i] = g_betas[0] * g_z[i];
}

// ---------------- host launcher ----------------
extern "C" void kernel_launch(void* const* d_in, const int* in_sizes, int n_in,
                              void* d_out, int out_size) {
    const float* x    = (const float*)d_in[0];
    const void*  ei   = d_in[1];
    const float* Win  = (const float*)d_in[2];
    const float* b_in = (const float*)d_in[3];
    const float* Wq   = (const float*)d_in[4];
    const float* bq   = (const float*)d_in[5];
    const float* Wk   = (const float*)d_in[6];
    const float* bk   = (const float*)d_in[7];
    const float* Wv   = (const float*)d_in[8];
    const float* bv   = (const float*)d_in[9];
    const float* Wsk  = (const float*)d_in[10];
    const float* bsk  = (const float*)d_in[11];
    const float* W1   = (const float*)d_in[12];
    const float* b1   = (const float*)d_in[13];
    const float* W2   = (const float*)d_in[14];
    const float* b2   = (const float*)d_in[15];
    const float* g1   = (const float*)d_in[16];
    const float* bt1  = (const float*)d_in[17];
    const float* g2   = (const float*)d_in[18];
    const float* bt2  = (const float*)d_in[19];
    const float* beta = (const float*)d_in[20];
    float* out = (float*)d_out;

    float *z, *h, *t, *u;
    __half* wt;
    cudaGetSymbolAddress((void**)&z, g_z);
    cudaGetSymbolAddress((void**)&h, g_h);
    cudaGetSymbolAddress((void**)&t, g_t);
    cudaGetSymbolAddress((void**)&u, g_u);
    cudaGetSymbolAddress((void**)&wt, g_wt);

    const int GM = (NN + BM - 1) / BM;  // 391

    // captures land on launch index 3 -> representative GEMM there
    sniff_kernel<<<1, 32>>>((const unsigned*)ei);                        // 0
    beta_softmax<<<1, 32>>>(beta);                                       // 1
    convW<<<(TOTW + 255) / 256, 256>>>(Win, Wq, Wk, Wv, Wsk, W1, W2);    // 2
    gemm_f16<1><<<dim3(GM, 1), 256>>>(x, wt, b_in, z, NN, HIDC, HIDC);   // 3
    gemm_qkvsk<<<dim3(GM, 4), 256>>>(z, wt, bq, bk, bv, bsk, 0);         // 4

    init_acc<<<(NN * HIDC + 255) / 256, 256>>>(out);
    convert_edges<<<(EE + 255) / 256, 256>>>(ei);

    // CSR build (once; needed before first attn)
    k_clear_deg<<<(NN + 255) / 256, 256>>>();
    k_hist<<<(EE + 255) / 256, 256>>>();
    k_chunksum<<<NCHK, CHUNK>>>();
    k_scanchunks<<<1, 32>>>();
    k_rowptr<<<NCHK, CHUNK>>>();
    k_fill<<<(EE + 255) / 256, 256>>>();

    for (int l = 0; l < NLAYERS; l++) {
        if (l > 0)
            gemm_qkvsk<<<dim3(GM, 4), 256>>>(z, wt, bq, bk, bv, bsk, l);

        attn_fused<<<(NN * 32 + 255) / 256, 256>>>();

        ln3_kernel<<<(NN + 7) / 8, 256>>>(g1 + l * HIDC, bt1 + l * HIDC);

        gemm_f16<2><<<dim3(GM, 2), 256>>>(h, wt + OFF_W1 + (size_t)l * HIDC * FFC,
                                          b1 + l * FFC, t, NN, HIDC, FFC);
        gemm_f16<0><<<dim3(GM, 1), 256>>>(t, wt + OFF_W2 + (size_t)l * FFC * HIDC,
                                          b2 + l * HIDC, u, NN, FFC, HIDC);

        lnacc_kernel<<<(NN + 7) / 8, 256>>>(g2 + l * HIDC, bt2 + l * HIDC, out, l + 1);
    }
}

// round 13
// speedup vs baseline: 1.1848x; 1.0047x over previous
#include <cuda_runtime.h>
#include <cuda_fp16.h>
#include <math.h>
#include <stdint.h>

#define NN 50000
#define EE 800000
#define HIDC 128
#define FFC 256
#define NLAYERS 6
#define EPSLN 1e-5f

// ---------------- scratch (device globals; no allocation allowed) ----------------
__device__ float g_z[NN * HIDC];
__device__ float g_q[NN * HIDC];
__device__ float g_k[NN * HIDC];
__device__ float g_v[NN * HIDC];
__device__ float g_sk[NN * HIDC];
__device__ float g_attn[NN * HIDC];
__device__ float g_h[NN * HIDC];
__device__ float g_t[NN * FFC];
__device__ float g_u[NN * HIDC];
__device__ int g_src[EE];
__device__ int g_dst[EE];
__device__ int g_deg[NN];
__device__ int g_rowptr[NN + 1];
__device__ int g_cur[NN];
__device__ int g_csrc[EE];
__device__ int g_csums[128];
__device__ float g_betas[NLAYERS + 2];
__device__ int g_flag[1];

// fp16-preconverted weights, FRAGMENT-MAJOR (m16n8k16) layout; element offsets
#define OFF_WQ  16384
#define OFF_WK  (OFF_WQ + NLAYERS * HIDC * HIDC)
#define OFF_WV  (OFF_WK + NLAYERS * HIDC * HIDC)
#define OFF_WSK (OFF_WV + NLAYERS * HIDC * HIDC)
#define OFF_W1  (OFF_WSK + NLAYERS * HIDC * HIDC)
#define OFF_W2  (OFF_W1 + NLAYERS * HIDC * FFC)
#define TOTW    (OFF_W2 + NLAYERS * FFC * HIDC)
__device__ __half g_wt[TOTW];

#define CHUNK 512
#define NCHK ((NN + CHUNK - 1) / CHUNK)   // 98

// ---------------- helpers ----------------
__device__ __forceinline__ void mma_f16(float* d, const uint32_t* a, const uint32_t* b) {
    asm volatile(
        "mma.sync.aligned.m16n8k16.row.col.f32.f16.f16.f32 "
        "{%0,%1,%2,%3}, {%4,%5,%6,%7}, {%8,%9}, {%0,%1,%2,%3};"
        : "+f"(d[0]), "+f"(d[1]), "+f"(d[2]), "+f"(d[3])
        : "r"(a[0]), "r"(a[1]), "r"(a[2]), "r"(a[3]), "r"(b[0]), "r"(b[1]));
}

__device__ __forceinline__ void cp16(uint32_t saddr, const void* g) {
    asm volatile("cp.async.ca.shared.global [%0], [%1], 16;" ::"r"(saddr), "l"(g));
}
__device__ __forceinline__ void cp_commit() { asm volatile("cp.async.commit_group;"); }
__device__ __forceinline__ void cp_wait0() { asm volatile("cp.async.wait_group 0;"); }

// ---------------- edge index dtype sniff + convert ----------------
__global__ void sniff_kernel(const unsigned* __restrict__ w) {
    if (threadIdx.x == 0 && blockIdx.x == 0) {
        int is64 = 1;
        for (int i = 1; i < 64; i += 2)
            if (w[i] != 0u) { is64 = 0; break; }
        g_flag[0] = is64;
    }
}

__global__ __launch_bounds__(256) void convert_edges(const void* __restrict__ ei) {
    int e = blockIdx.x * blockDim.x + threadIdx.x;
    if (e >= EE) return;
    if (g_flag[0]) {
        const long long* p = (const long long*)ei;
        g_src[e] = (int)p[e];
        g_dst[e] = (int)p[EE + e];
    } else {
        const int* p = (const int*)ei;
        g_src[e] = p[e];
        g_dst[e] = p[EE + e];
    }
}

__global__ void beta_softmax(const float* __restrict__ beta) {
    if (threadIdx.x == 0 && blockIdx.x == 0) {
        float m = -1e30f;
        for (int i = 0; i < NLAYERS + 1; i++) m = fmaxf(m, beta[i]);
        float s = 0.f;
        for (int i = 0; i < NLAYERS + 1; i++) {
            float e = expf(beta[i] - m);
            g_betas[i] = e;
            s += e;
        }
        for (int i = 0; i < NLAYERS + 1; i++) g_betas[i] /= s;
    }
}

// ---------------- weight fp16 convert + m16n8k16 fragment-major permute -------
__device__ __forceinline__ int permW16(int k, int n, int N) {
    return (k >> 4) * 16 * N + (n >> 3) * 128 +
           ((n & 7) * 4 + ((k & 7) >> 1)) * 4 + ((k >> 3) & 1) * 2 + (k & 1);
}

__global__ __launch_bounds__(256) void convW(
    const float* __restrict__ Win, const float* __restrict__ Wq,
    const float* __restrict__ Wk, const float* __restrict__ Wv,
    const float* __restrict__ Wsk, const float* __restrict__ W1,
    const float* __restrict__ W2) {
    int i = blockIdx.x * blockDim.x + threadIdx.x;
    if (i >= TOTW) return;
    const float* src;
    int base, off, N, matsz;
    if (i < OFF_WQ)       { src = Win; base = 0;       off = i;           N = 128; matsz = HIDC * HIDC; }
    else if (i < OFF_WK)  { src = Wq;  base = OFF_WQ;  off = i - OFF_WQ;  N = 128; matsz = HIDC * HIDC; }
    else if (i < OFF_WV)  { src = Wk;  base = OFF_WK;  off = i - OFF_WK;  N = 128; matsz = HIDC * HIDC; }
    else if (i < OFF_WSK) { src = Wv;  base = OFF_WV;  off = i - OFF_WV;  N = 128; matsz = HIDC * HIDC; }
    else if (i < OFF_W1)  { src = Wsk; base = OFF_WSK; off = i - OFF_WSK; N = 128; matsz = HIDC * HIDC; }
    else if (i < OFF_W2)  { src = W1;  base = OFF_W1;  off = i - OFF_W1;  N = 256; matsz = HIDC * FFC; }
    else                  { src = W2;  base = OFF_W2;  off = i - OFF_W2;  N = 128; matsz = FFC * HIDC; }
    int l = off / matsz;
    int o2 = off - l * matsz;
    int k = o2 / N, n = o2 - k * N;
    g_wt[base + l * matsz + permW16(k, n, N)] = __float2half_rn(src[off]);
}

// ---------------- CSR build ----------------
__global__ __launch_bounds__(256) void k_clear_deg() {
    int i = blockIdx.x * blockDim.x + threadIdx.x;
    if (i < NN) g_deg[i] = 0;
}
__global__ __launch_bounds__(256) void k_hist() {
    int e = blockIdx.x * blockDim.x + threadIdx.x;
    if (e < EE) atomicAdd(&g_deg[g_dst[e]], 1);
}
__global__ __launch_bounds__(CHUNK) void k_chunksum() {
    __shared__ int sh[CHUNK];
    int tid = threadIdx.x;
    int i = blockIdx.x * CHUNK + tid;
    sh[tid] = (i < NN) ? g_deg[i] : 0;
    __syncthreads();
    for (int off = CHUNK / 2; off > 0; off >>= 1) {
        if (tid < off) sh[tid] += sh[tid + off];
        __syncthreads();
    }
    if (tid == 0) g_csums[blockIdx.x] = sh[0];
}
__global__ void k_scanchunks() {
    if (threadIdx.x == 0 && blockIdx.x == 0) {
        int run = 0;
        for (int c = 0; c < NCHK; c++) {
            int v = g_csums[c];
            g_csums[c] = run;
            run += v;
        }
        g_rowptr[NN] = run;
    }
}
__global__ __launch_bounds__(CHUNK) void k_rowptr() {
    __shared__ int sh[CHUNK];
    int tid = threadIdx.x;
    int i = blockIdx.x * CHUNK + tid;
    int v = (i < NN) ? g_deg[i] : 0;
    sh[tid] = v;
    __syncthreads();
    for (int off = 1; off < CHUNK; off <<= 1) {
        int t = (tid >= off) ? sh[tid - off] : 0;
        __syncthreads();
        sh[tid] += t;
        __syncthreads();
    }
    if (i < NN) {
        int excl = sh[tid] - v + g_csums[blockIdx.x];
        g_rowptr[i] = excl;
        g_cur[i] = excl;
    }
}
__global__ __launch_bounds__(256) void k_fill() {
    int e = blockIdx.x * blockDim.x + threadIdx.x;
    if (e >= EE) return;
    int slot = atomicAdd(&g_cur[g_dst[e]], 1);
    g_csrc[slot] = g_src[e];
}

// ---------------- FP16 GEMM (m16n8k16), BK=32, fragment-major smem -----------
// 256 thr, 8 warps (2x4), warp tile 64x32.
// A buffer 8KB: 2 kc2 x 8 m16-chunks x 512B; B buffer 8KB: 2 kc2 x 16 n8 x 256B.
#define BM 128
#define BN 128
#define BK 32
#define ABUF 4096   // halves per A buffer
#define BBUF 4096   // halves per B buffer

__device__ __forceinline__ void ldA(
    const float* __restrict__ A, int M, int K, int m0, int kc, int tid,
    float4 ar[4]) {
#pragma unroll
    for (int i = 0; i < 4; i++) {
        int f = tid + i * 256;
        int m = f >> 3, k4 = (f & 7) * 4;
        ar[i] = (m0 + m < M)
                    ? *(const float4*)(A + (size_t)(m0 + m) * K + kc + k4)
                    : make_float4(0.f, 0.f, 0.f, 0.f);
    }
}

// A staging: thread-f row m, cols k4..k4+3 -> chunk (kc2*8+mb),
// slots (g*4+t), (g*4+t+1); reg = h + 2*kb  (kc2=k4>>4, within-chunk k4r=k4&15)
__device__ __forceinline__ void stA(__half2* As2, int tid, const float4 ar[4]) {
#pragma unroll
    for (int i = 0; i < 4; i++) {
        int f = tid + i * 256;
        int m = f >> 3, k4 = (f & 7) * 4;
        int kc2 = k4 >> 4, k4r = k4 & 15;
        int g = m & 7, h = (m >> 3) & 1, mb = m >> 4;
        int t = (k4r & 7) >> 1;            // 0 or 2
        int kb = (k4r >> 3) & 1;
        int reg = h + 2 * kb;
        int cb = (kc2 * 8 + mb) * 128;     // chunk base in half2
        __half2 p0 = __floats2half2_rn(ar[i].x, ar[i].y);
        __half2 p1 = __floats2half2_rn(ar[i].z, ar[i].w);
        As2[cb + (g * 4 + t) * 4 + reg] = p0;
        As2[cb + (g * 4 + t + 1) * 4 + reg] = p1;
    }
}

// B copy: two consecutive 16-K iter-blocks, each one contiguous 4KB region.
__device__ __forceinline__ void cpB(uint32_t bs_addr, const __half* __restrict__ Bmat,
                                    int N, int n0, int kc, int tid) {
    const __half* gp0 = Bmat + (size_t)kc * N + (n0 >> 3) * 128;
    const __half* gp1 = Bmat + (size_t)(kc + 16) * N + (n0 >> 3) * 128;
#pragma unroll
    for (int i = 0; i < 2; i++) {
        int idx = tid + i * 256;           // 0..511
        const __half* gp = (idx < 256) ? (gp0 + idx * 8) : (gp1 + (idx - 256) * 8);
        cp16(bs_addr + idx * 16, gp);
    }
}

template <int ACT>
__device__ __forceinline__ void gemm_core(
    const float* __restrict__ A, const __half* __restrict__ Bmat,
    const float* __restrict__ bias, float* __restrict__ C,
    int M, int K, int Nld, int m0, int n0,
    __half* As, __half* Bs, uint32_t bs_addr) {
    int tid = threadIdx.x;
    int warp = tid >> 5, lane = tid & 31;
    int wm = (warp >> 2) * 64, wn = (warp & 3) * 32;

    float acc[4][4][4];
#pragma unroll
    for (int a = 0; a < 4; a++)
#pragma unroll
        for (int b = 0; b < 4; b++)
#pragma unroll
            for (int c = 0; c < 4; c++) acc[a][b][c] = 0.f;

    float4 ar[4];
    ldA(A, M, K, m0, 0, tid, ar);
    cpB(bs_addr, Bmat, Nld, n0, 0, tid);
    stA((__half2*)As, tid, ar);
    cp_commit();
    cp_wait0();
    __syncthreads();

    int nit = K / BK;
    for (int it = 0; it < nit; it++) {
        int cur = it & 1;
        const __half* Ac = As + cur * ABUF;
        const __half* Bc = Bs + cur * BBUF;
        if (it + 1 < nit) {
            ldA(A, M, K, m0, (it + 1) * BK, tid, ar);
            cpB(bs_addr + (cur ^ 1) * (BBUF * 2), Bmat, Nld, n0, (it + 1) * BK, tid);
            cp_commit();
        }

#pragma unroll
        for (int kc2 = 0; kc2 < 2; kc2++) {
            uint4 af[4];
#pragma unroll
            for (int tm = 0; tm < 4; tm++) {
                int mb = (wm >> 4) + tm;
                af[tm] = *(const uint4*)(Ac + (kc2 * 8 + mb) * 256 + lane * 8);
            }
            uint2 bf[4];
#pragma unroll
            for (int tn = 0; tn < 4; tn++) {
                int nb = (wn >> 3) + tn;
                bf[tn] = *(const uint2*)(Bc + (kc2 * 16 + nb) * 128 + lane * 4);
            }
#pragma unroll
            for (int tm = 0; tm < 4; tm++)
#pragma unroll
                for (int tn = 0; tn < 4; tn++)
                    mma_f16(acc[tm][tn], (const uint32_t*)&af[tm],
                            (const uint32_t*)&bf[tn]);
        }

        if (it + 1 < nit) stA((__half2*)(As + (cur ^ 1) * ABUF), tid, ar);
        cp_wait0();
        __syncthreads();
    }

    // epilogue: c0,c1 row g cols 2t,2t+1 ; c2,c3 row g+8
    int gg = lane >> 2, tt = lane & 3;
#pragma unroll
    for (int tm = 0; tm < 4; tm++) {
        int r0 = m0 + wm + tm * 16 + gg;
        int r1 = r0 + 8;
#pragma unroll
        for (int tn = 0; tn < 4; tn++) {
            int cb = n0 + wn + tn * 8 + 2 * tt;
            float b0 = __ldg(bias + cb);
            float b1 = __ldg(bias + cb + 1);
            float v00 = acc[tm][tn][0] + b0;
            float v01 = acc[tm][tn][1] + b1;
            float v10 = acc[tm][tn][2] + b0;
            float v11 = acc[tm][tn][3] + b1;
            if (ACT == 1) {
                v00 = fmaxf(v00, 0.f); v01 = fmaxf(v01, 0.f);
                v10 = fmaxf(v10, 0.f); v11 = fmaxf(v11, 0.f);
            }
            if (ACT == 2) {
                v00 = 0.5f * v00 * (1.f + erff(v00 * 0.70710678118654752f));
                v01 = 0.5f * v01 * (1.f + erff(v01 * 0.70710678118654752f));
                v10 = 0.5f * v10 * (1.f + erff(v10 * 0.70710678118654752f));
                v11 = 0.5f * v11 * (1.f + erff(v11 * 0.70710678118654752f));
            }
            if (r0 < M) *(float2*)(C + (size_t)r0 * Nld + cb) = make_float2(v00, v01);
            if (r1 < M) *(float2*)(C + (size_t)r1 * Nld + cb) = make_float2(v10, v11);
        }
    }
}

template <int ACT>
__global__ __launch_bounds__(256, 2) void gemm_f16(
    const float* __restrict__ A, const __half* __restrict__ B,
    const float* __restrict__ bias, float* __restrict__ C,
    int M, int K, int Nld) {
    __shared__ __align__(16) __half As[2 * ABUF];
    __shared__ __align__(16) __half Bs[2 * BBUF];
    uint32_t bs = (uint32_t)__cvta_generic_to_shared(Bs);
    gemm_core<ACT>(A, B, bias, C, M, K, Nld, blockIdx.x * BM, blockIdx.y * BN,
                   As, Bs, bs);
}

// fused Q/K/V/SK projection: grid.y in [0,4) selects operator
__global__ __launch_bounds__(256, 2) void gemm_qkvsk(
    const float* __restrict__ A, const __half* __restrict__ wt,
    const float* __restrict__ bq, const float* __restrict__ bk,
    const float* __restrict__ bv, const float* __restrict__ bsk, int l) {
    __shared__ __align__(16) __half As[2 * ABUF];
    __shared__ __align__(16) __half Bs[2 * BBUF];
    uint32_t bs = (uint32_t)__cvta_generic_to_shared(Bs);
    const __half* B;
    const float* bias;
    float* C;
    switch (blockIdx.y) {
        case 0: B = wt + OFF_WQ;  bias = bq;  C = g_q;  break;
        case 1: B = wt + OFF_WK;  bias = bk;  C = g_k;  break;
        case 2: B = wt + OFF_WV;  bias = bv;  C = g_v;  break;
        default: B = wt + OFF_WSK; bias = bsk; C = g_sk; break;
    }
    B += (size_t)l * HIDC * HIDC;
    bias += l * HIDC;
    gemm_core<0>(A, B, bias, C, NN, HIDC, HIDC, blockIdx.x * BM, 0, As, Bs, bs);
}

// ---------------- fused attention: warp/node, online softmax, 4-edge unroll ----
__global__ __launch_bounds__(256) void attn_fused() {
    int node = (blockIdx.x * blockDim.x + threadIdx.x) >> 5;
    if (node >= NN) return;
    int lane = threadIdx.x & 31;
    int beg = g_rowptr[node], end = g_rowptr[node + 1];
    size_t qb = (size_t)node * HIDC + lane * 4;
    float4 qv = *(const float4*)(g_q + qb);
    float m = -INFINITY, l = 0.f;
    float4 acc = make_float4(0.f, 0.f, 0.f, 0.f);
    int e = beg;
    for (; e + 3 < end; e += 4) {
        int s0 = g_csrc[e], s1 = g_csrc[e + 1], s2 = g_csrc[e + 2], s3 = g_csrc[e + 3];
        size_t b0 = (size_t)s0 * HIDC + lane * 4;
        size_t b1 = (size_t)s1 * HIDC + lane * 4;
        size_t b2 = (size_t)s2 * HIDC + lane * 4;
        size_t b3 = (size_t)s3 * HIDC + lane * 4;
        float4 k0 = *(const float4*)(g_k + b0);
        float4 k1 = *(const float4*)(g_k + b1);
        float4 k2 = *(const float4*)(g_k + b2);
        float4 k3 = *(const float4*)(g_k + b3);
        float4 v0 = *(const float4*)(g_v + b0);
        float4 v1 = *(const float4*)(g_v + b1);
        float4 v2 = *(const float4*)(g_v + b2);
        float4 v3 = *(const float4*)(g_v + b3);
        float p0 = qv.x * k0.x + qv.y * k0.y + qv.z * k0.z + qv.w * k0.w;
        float p1 = qv.x * k1.x + qv.y * k1.y + qv.z * k1.z + qv.w * k1.w;
        float p2 = qv.x * k2.x + qv.y * k2.y + qv.z * k2.z + qv.w * k2.w;
        float p3 = qv.x * k3.x + qv.y * k3.y + qv.z * k3.z + qv.w * k3.w;
#pragma unroll
        for (int o = 8; o > 0; o >>= 1) {
            p0 += __shfl_xor_sync(0xffffffffu, p0, o, 16);
            p1 += __shfl_xor_sync(0xffffffffu, p1, o, 16);
            p2 += __shfl_xor_sync(0xffffffffu, p2, o, 16);
            p3 += __shfl_xor_sync(0xffffffffu, p3, o, 16);
        }
        float sc0 = p0 * 0.125f, sc1 = p1 * 0.125f;
        float sc2 = p2 * 0.125f, sc3 = p3 * 0.125f;
        float mn = fmaxf(fmaxf(m, fmaxf(sc0, sc1)), fmaxf(sc2, sc3));
        float scale = __expf(m - mn);
        float w0 = __expf(sc0 - mn);
        float w1 = __expf(sc1 - mn);
        float w2 = __expf(sc2 - mn);
        float w3 = __expf(sc3 - mn);
        l = l * scale + (w0 + w1) + (w2 + w3);
        acc.x = acc.x * scale + (w0 * v0.x + w1 * v1.x) + (w2 * v2.x + w3 * v3.x);
        acc.y = acc.y * scale + (w0 * v0.y + w1 * v1.y) + (w2 * v2.y + w3 * v3.y);
        acc.z = acc.z * scale + (w0 * v0.z + w1 * v1.z) + (w2 * v2.z + w3 * v3.z);
        acc.w = acc.w * scale + (w0 * v0.w + w1 * v1.w) + (w2 * v2.w + w3 * v3.w);
        m = mn;
    }
    for (; e < end; e++) {
        int s = g_csrc[e];
        size_t sb = (size_t)s * HIDC + lane * 4;
        float4 kv = *(const float4*)(g_k + sb);
        float4 vv = *(const float4*)(g_v + sb);
        float p = qv.x * kv.x + qv.y * kv.y + qv.z * kv.z + qv.w * kv.w;
#pragma unroll
        for (int o = 8; o > 0; o >>= 1) p += __shfl_xor_sync(0xffffffffu, p, o, 16);
        float sc = p * 0.125f;
        float mn = fmaxf(m, sc);
        float scale = __expf(m - mn);
        float w = __expf(sc - mn);
        l = l * scale + w;
        acc.x = acc.x * scale + w * vv.x;
        acc.y = acc.y * scale + w * vv.y;
        acc.z = acc.z * scale + w * vv.z;
        acc.w = acc.w * scale + w * vv.w;
        m = mn;
    }
    float inv = (l > 0.f) ? 1.f / l : 0.f;
    acc.x *= inv; acc.y *= inv; acc.z *= inv; acc.w *= inv;
    *(float4*)(g_attn + qb) = acc;
}

// ---------------- layernorm kernels (warp per row, 128 cols) ----------------
__global__ __launch_bounds__(256) void ln3_kernel(
    const float* __restrict__ g, const float* __restrict__ bt) {
    int row = (blockIdx.x * blockDim.x + threadIdx.x) >> 5;
    if (row >= NN) return;
    int lane = threadIdx.x & 31;
    size_t base = (size_t)row * HIDC + lane * 4;
    float4 a = *(const float4*)(g_z + base);
    float4 b = *(const float4*)(g_attn + base);
    float4 c = *(const float4*)(g_sk + base);
    float v0 = a.x + b.x + c.x, v1 = a.y + b.y + c.y;
    float v2 = a.z + b.z + c.z, v3 = a.w + b.w + c.w;
    float s = v0 + v1 + v2 + v3;
#pragma unroll
    for (int o = 16; o > 0; o >>= 1) s += __shfl_xor_sync(0xffffffffu, s, o);
    float mu = s * (1.f / HIDC);
    float d0 = v0 - mu, d1 = v1 - mu, d2 = v2 - mu, d3 = v3 - mu;
    float ss = d0 * d0 + d1 * d1 + d2 * d2 + d3 * d3;
#pragma unroll
    for (int o = 16; o > 0; o >>= 1) ss += __shfl_xor_sync(0xffffffffu, ss, o);
    float rs = rsqrtf(ss * (1.f / HIDC) + EPSLN);
    int col = lane * 4;
    float4 o4;
    o4.x = d0 * rs * g[col + 0] + bt[col + 0];
    o4.y = d1 * rs * g[col + 1] + bt[col + 1];
    o4.z = d2 * rs * g[col + 2] + bt[col + 2];
    o4.w = d3 * rs * g[col + 3] + bt[col + 3];
    *(float4*)(g_h + base) = o4;
}

// z = relu(LN(h+u)); out += betas[li]*z
__global__ __launch_bounds__(256) void lnacc_kernel(
    const float* __restrict__ g, const float* __restrict__ bt,
    float* __restrict__ out, int li) {
    int row = (blockIdx.x * blockDim.x + threadIdx.x) >> 5;
    if (row >= NN) return;
    int lane = threadIdx.x & 31;
    size_t base = (size_t)row * HIDC + lane * 4;
    float4 a = *(const float4*)(g_h + base);
    float4 b = *(const float4*)(g_u + base);
    float v0 = a.x + b.x, v1 = a.y + b.y, v2 = a.z + b.z, v3 = a.w + b.w;
    float s = v0 + v1 + v2 + v3;
#pragma unroll
    for (int o = 16; o > 0; o >>= 1) s += __shfl_xor_sync(0xffffffffu, s, o);
    float mu = s * (1.f / HIDC);
    float d0 = v0 - mu, d1 = v1 - mu, d2 = v2 - mu, d3 = v3 - mu;
    float ss = d0 * d0 + d1 * d1 + d2 * d2 + d3 * d3;
#pragma unroll
    for (int o = 16; o > 0; o >>= 1) ss += __shfl_xor_sync(0xffffffffu, ss, o);
    float rs = rsqrtf(ss * (1.f / HIDC) + EPSLN);
    int col = lane * 4;
    float z0 = fmaxf(d0 * rs * g[col + 0] + bt[col + 0], 0.f);
    float z1 = fmaxf(d1 * rs * g[col + 1] + bt[col + 1], 0.f);
    float z2 = fmaxf(d2 * rs * g[col + 2] + bt[col + 2], 0.f);
    float z3 = fmaxf(d3 * rs * g[col + 3] + bt[col + 3], 0.f);
    float bb = g_betas[li];
    *(float4*)(g_z + base) = make_float4(z0, z1, z2, z3);
    float4 oo = *(float4*)(out + base);
    oo.x += bb * z0; oo.y += bb * z1; oo.z += bb * z2; oo.w += bb * z3;
    *(float4*)(out + base) = oo;
}

__global__ __launch_bounds__(256) void init_acc(float* __restrict__ out) {
    int i = blockIdx.x * blockDim.x + threadIdx.x;
    if (i < NN * HIDC) out[i] = g_betas[0] * g_z[i];
}

// ---------------- host launcher ----------------
extern "C" void kernel_launch(void* const* d_in, const int* in_sizes, int n_in,
                              void* d_out, int out_size) {
    const float* x    = (const float*)d_in[0];
    const void*  ei   = d_in[1];
    const float* Win  = (const float*)d_in[2];
    const float* b_in = (const float*)d_in[3];
    const float* Wq   = (const float*)d_in[4];
    const float* bq   = (const float*)d_in[5];
    const float* Wk   = (const float*)d_in[6];
    const float* bk   = (const float*)d_in[7];
    const float* Wv   = (const float*)d_in[8];
    const float* bv   = (const float*)d_in[9];
    const float* Wsk  = (const float*)d_in[10];
    const float* bsk  = (const float*)d_in[11];
    const float* W1   = (const float*)d_in[12];
    const float* b1   = (const float*)d_in[13];
    const float* W2   = (const float*)d_in[14];
    const float* b2   = (const float*)d_in[15];
    const float* g1   = (const float*)d_in[16];
    const float* bt1  = (const float*)d_in[17];
    const float* g2   = (const float*)d_in[18];
    const float* bt2  = (const float*)d_in[19];
    const float* beta = (const float*)d_in[20];
    float* out = (float*)d_out;

    float *z, *h, *t, *u;
    __half* wt;
    cudaGetSymbolAddress((void**)&z, g_z);
    cudaGetSymbolAddress((void**)&h, g_h);
    cudaGetSymbolAddress((void**)&t, g_t);
    cudaGetSymbolAddress((void**)&u, g_u);
    cudaGetSymbolAddress((void**)&wt, g_wt);

    const int GM = (NN + BM - 1) / BM;  // 391

    // captures land on launch index 3 -> representative GEMM there
    sniff_kernel<<<1, 32>>>((const unsigned*)ei);                        // 0
    beta_softmax<<<1, 32>>>(beta);                                       // 1
    convW<<<(TOTW + 255) / 256, 256>>>(Win, Wq, Wk, Wv, Wsk, W1, W2);    // 2
    gemm_f16<1><<<dim3(GM, 1), 256>>>(x, wt, b_in, z, NN, HIDC, HIDC);   // 3
    gemm_qkvsk<<<dim3(GM, 4), 256>>>(z, wt, bq, bk, bv, bsk, 0);         // 4

    init_acc<<<(NN * HIDC + 255) / 256, 256>>>(out);
    convert_edges<<<(EE + 255) / 256, 256>>>(ei);

    // CSR build (once; needed before first attn)
    k_clear_deg<<<(NN + 255) / 256, 256>>>();
    k_hist<<<(EE + 255) / 256, 256>>>();
    k_chunksum<<<NCHK, CHUNK>>>();
    k_scanchunks<<<1, 32>>>();
    k_rowptr<<<NCHK, CHUNK>>>();
    k_fill<<<(EE + 255) / 256, 256>>>();

    for (int l = 0; l < NLAYERS; l++) {
        if (l > 0)
            gemm_qkvsk<<<dim3(GM, 4), 256>>>(z, wt, bq, bk, bv, bsk, l);

        attn_fused<<<(NN * 32 + 255) / 256, 256>>>();

        ln3_kernel<<<(NN + 7) / 8, 256>>>(g1 + l * HIDC, bt1 + l * HIDC);

        gemm_f16<2><<<dim3(GM, 2), 256>>>(h, wt + OFF_W1 + (size_t)l * HIDC * FFC,
                                          b1 + l * FFC, t, NN, HIDC, FFC);
        gemm_f16<0><<<dim3(GM, 1), 256>>>(t, wt + OFF_W2 + (size_t)l * FFC * HIDC,
                                          b2 + l * HIDC, u, NN, FFC, HIDC);

        lnacc_kernel<<<(NN + 7) / 8, 256>>>(g2 + l * HIDC, bt2 + l * HIDC, out, l + 1);
    }
}

// round 14
// speedup vs baseline: 1.2899x; 1.0888x over previous
#include <cuda_runtime.h>
#include <cuda_fp16.h>
#include <math.h>
#include <stdint.h>

#define NN 50000
#define EE 800000
#define HIDC 128
#define FFC 256
#define NLAYERS 6
#define EPSLN 1e-5f

// ---------------- scratch (device globals; no allocation allowed) ----------------
__device__ float g_z[NN * HIDC];
__device__ float g_q[NN * HIDC];
__device__ float g_k[NN * HIDC];
__device__ float g_v[NN * HIDC];
__device__ float g_sk[NN * HIDC];
__device__ float g_h[NN * HIDC];
__device__ float g_t[NN * FFC];
__device__ float g_u[NN * HIDC];
__device__ int g_src[EE];
__device__ int g_dst[EE];
__device__ int g_deg[NN];
__device__ int g_rowptr[NN + 1];
__device__ int g_cur[NN];
__device__ int g_csrc[EE];
__device__ int g_csums[128];
__device__ float g_betas[NLAYERS + 2];
__device__ int g_flag[1];

// fp16-preconverted weights, FRAGMENT-MAJOR (m16n8k16) layout; element offsets
#define OFF_WQ  16384
#define OFF_WK  (OFF_WQ + NLAYERS * HIDC * HIDC)
#define OFF_WV  (OFF_WK + NLAYERS * HIDC * HIDC)
#define OFF_WSK (OFF_WV + NLAYERS * HIDC * HIDC)
#define OFF_W1  (OFF_WSK + NLAYERS * HIDC * HIDC)
#define OFF_W2  (OFF_W1 + NLAYERS * HIDC * FFC)
#define TOTW    (OFF_W2 + NLAYERS * FFC * HIDC)
__device__ __half g_wt[TOTW];

#define CHUNK 512
#define NCHK ((NN + CHUNK - 1) / CHUNK)   // 98

// ---------------- helpers ----------------
__device__ __forceinline__ void mma_f16(float* d, const uint32_t* a, const uint32_t* b) {
    asm volatile(
        "mma.sync.aligned.m16n8k16.row.col.f32.f16.f16.f32 "
        "{%0,%1,%2,%3}, {%4,%5,%6,%7}, {%8,%9}, {%0,%1,%2,%3};"
        : "+f"(d[0]), "+f"(d[1]), "+f"(d[2]), "+f"(d[3])
        : "r"(a[0]), "r"(a[1]), "r"(a[2]), "r"(a[3]), "r"(b[0]), "r"(b[1]));
}

__device__ __forceinline__ void cp16(uint32_t saddr, const void* g) {
    asm volatile("cp.async.ca.shared.global [%0], [%1], 16;" ::"r"(saddr), "l"(g));
}
__device__ __forceinline__ void cp_commit() { asm volatile("cp.async.commit_group;"); }
__device__ __forceinline__ void cp_wait0() { asm volatile("cp.async.wait_group 0;"); }

// ---------------- edge index dtype sniff + convert ----------------
__global__ void sniff_kernel(const unsigned* __restrict__ w) {
    if (threadIdx.x == 0 && blockIdx.x == 0) {
        int is64 = 1;
        for (int i = 1; i < 64; i += 2)
            if (w[i] != 0u) { is64 = 0; break; }
        g_flag[0] = is64;
    }
}

__global__ __launch_bounds__(256) void convert_edges(const void* __restrict__ ei) {
    int e = blockIdx.x * blockDim.x + threadIdx.x;
    if (e >= EE) return;
    if (g_flag[0]) {
        const long long* p = (const long long*)ei;
        g_src[e] = (int)p[e];
        g_dst[e] = (int)p[EE + e];
    } else {
        const int* p = (const int*)ei;
        g_src[e] = p[e];
        g_dst[e] = p[EE + e];
    }
}

__global__ void beta_softmax(const float* __restrict__ beta) {
    if (threadIdx.x == 0 && blockIdx.x == 0) {
        float m = -1e30f;
        for (int i = 0; i < NLAYERS + 1; i++) m = fmaxf(m, beta[i]);
        float s = 0.f;
        for (int i = 0; i < NLAYERS + 1; i++) {
            float e = expf(beta[i] - m);
            g_betas[i] = e;
            s += e;
        }
        for (int i = 0; i < NLAYERS + 1; i++) g_betas[i] /= s;
    }
}

// ---------------- weight fp16 convert + m16n8k16 fragment-major permute -------
__device__ __forceinline__ int permW16(int k, int n, int N) {
    return (k >> 4) * 16 * N + (n >> 3) * 128 +
           ((n & 7) * 4 + ((k & 7) >> 1)) * 4 + ((k >> 3) & 1) * 2 + (k & 1);
}

__global__ __launch_bounds__(256) void convW(
    const float* __restrict__ Win, const float* __restrict__ Wq,
    const float* __restrict__ Wk, const float* __restrict__ Wv,
    const float* __restrict__ Wsk, const float* __restrict__ W1,
    const float* __restrict__ W2) {
    int i = blockIdx.x * blockDim.x + threadIdx.x;
    if (i >= TOTW) return;
    const float* src;
    int base, off, N, matsz;
    if (i < OFF_WQ)       { src = Win; base = 0;       off = i;           N = 128; matsz = HIDC * HIDC; }
    else if (i < OFF_WK)  { src = Wq;  base = OFF_WQ;  off = i - OFF_WQ;  N = 128; matsz = HIDC * HIDC; }
    else if (i < OFF_WV)  { src = Wk;  base = OFF_WK;  off = i - OFF_WK;  N = 128; matsz = HIDC * HIDC; }
    else if (i < OFF_WSK) { src = Wv;  base = OFF_WV;  off = i - OFF_WV;  N = 128; matsz = HIDC * HIDC; }
    else if (i < OFF_W1)  { src = Wsk; base = OFF_WSK; off = i - OFF_WSK; N = 128; matsz = HIDC * HIDC; }
    else if (i < OFF_W2)  { src = W1;  base = OFF_W1;  off = i - OFF_W1;  N = 256; matsz = HIDC * FFC; }
    else                  { src = W2;  base = OFF_W2;  off = i - OFF_W2;  N = 128; matsz = FFC * HIDC; }
    int l = off / matsz;
    int o2 = off - l * matsz;
    int k = o2 / N, n = o2 - k * N;
    g_wt[base + l * matsz + permW16(k, n, N)] = __float2half_rn(src[off]);
}

// ---------------- CSR build ----------------
__global__ __launch_bounds__(256) void k_clear_deg() {
    int i = blockIdx.x * blockDim.x + threadIdx.x;
    if (i < NN) g_deg[i] = 0;
}
__global__ __launch_bounds__(256) void k_hist() {
    int e = blockIdx.x * blockDim.x + threadIdx.x;
    if (e < EE) atomicAdd(&g_deg[g_dst[e]], 1);
}
__global__ __launch_bounds__(CHUNK) void k_chunksum() {
    __shared__ int sh[CHUNK];
    int tid = threadIdx.x;
    int i = blockIdx.x * CHUNK + tid;
    sh[tid] = (i < NN) ? g_deg[i] : 0;
    __syncthreads();
    for (int off = CHUNK / 2; off > 0; off >>= 1) {
        if (tid < off) sh[tid] += sh[tid + off];
        __syncthreads();
    }
    if (tid == 0) g_csums[blockIdx.x] = sh[0];
}
__global__ void k_scanchunks() {
    if (threadIdx.x == 0 && blockIdx.x == 0) {
        int run = 0;
        for (int c = 0; c < NCHK; c++) {
            int v = g_csums[c];
            g_csums[c] = run;
            run += v;
        }
        g_rowptr[NN] = run;
    }
}
__global__ __launch_bounds__(CHUNK) void k_rowptr() {
    __shared__ int sh[CHUNK];
    int tid = threadIdx.x;
    int i = blockIdx.x * CHUNK + tid;
    int v = (i < NN) ? g_deg[i] : 0;
    sh[tid] = v;
    __syncthreads();
    for (int off = 1; off < CHUNK; off <<= 1) {
        int t = (tid >= off) ? sh[tid - off] : 0;
        __syncthreads();
        sh[tid] += t;
        __syncthreads();
    }
    if (i < NN) {
        int excl = sh[tid] - v + g_csums[blockIdx.x];
        g_rowptr[i] = excl;
        g_cur[i] = excl;
    }
}
__global__ __launch_bounds__(256) void k_fill() {
    int e = blockIdx.x * blockDim.x + threadIdx.x;
    if (e >= EE) return;
    int slot = atomicAdd(&g_cur[g_dst[e]], 1);
    g_csrc[slot] = g_src[e];
}

// ---------------- FP16 GEMM (m16n8k16), BK=32, fragment-major smem -----------
#define BM 128
#define BN 128
#define BK 32
#define ABUF 4096   // halves per A buffer
#define BBUF 4096   // halves per B buffer

__device__ __forceinline__ void ldA(
    const float* __restrict__ A, int M, int K, int m0, int kc, int tid,
    float4 ar[4]) {
#pragma unroll
    for (int i = 0; i < 4; i++) {
        int f = tid + i * 256;
        int m = f >> 3, k4 = (f & 7) * 4;
        ar[i] = (m0 + m < M)
                    ? *(const float4*)(A + (size_t)(m0 + m) * K + kc + k4)
                    : make_float4(0.f, 0.f, 0.f, 0.f);
    }
}

__device__ __forceinline__ void stA(__half2* As2, int tid, const float4 ar[4]) {
#pragma unroll
    for (int i = 0; i < 4; i++) {
        int f = tid + i * 256;
        int m = f >> 3, k4 = (f & 7) * 4;
        int kc2 = k4 >> 4, k4r = k4 & 15;
        int g = m & 7, h = (m >> 3) & 1, mb = m >> 4;
        int t = (k4r & 7) >> 1;            // 0 or 2
        int kb = (k4r >> 3) & 1;
        int reg = h + 2 * kb;
        int cb = (kc2 * 8 + mb) * 128;     // chunk base in half2
        __half2 p0 = __floats2half2_rn(ar[i].x, ar[i].y);
        __half2 p1 = __floats2half2_rn(ar[i].z, ar[i].w);
        As2[cb + (g * 4 + t) * 4 + reg] = p0;
        As2[cb + (g * 4 + t + 1) * 4 + reg] = p1;
    }
}

__device__ __forceinline__ void cpB(uint32_t bs_addr, const __half* __restrict__ Bmat,
                                    int N, int n0, int kc, int tid) {
    const __half* gp0 = Bmat + (size_t)kc * N + (n0 >> 3) * 128;
    const __half* gp1 = Bmat + (size_t)(kc + 16) * N + (n0 >> 3) * 128;
#pragma unroll
    for (int i = 0; i < 2; i++) {
        int idx = tid + i * 256;           // 0..511
        const __half* gp = (idx < 256) ? (gp0 + idx * 8) : (gp1 + (idx - 256) * 8);
        cp16(bs_addr + idx * 16, gp);
    }
}

template <int ACT>
__device__ __forceinline__ void gemm_core(
    const float* __restrict__ A, const __half* __restrict__ Bmat,
    const float* __restrict__ bias, float* __restrict__ C,
    int M, int K, int Nld, int m0, int n0,
    __half* As, __half* Bs, uint32_t bs_addr) {
    int tid = threadIdx.x;
    int warp = tid >> 5, lane = tid & 31;
    int wm = (warp >> 2) * 64, wn = (warp & 3) * 32;

    float acc[4][4][4];
#pragma unroll
    for (int a = 0; a < 4; a++)
#pragma unroll
        for (int b = 0; b < 4; b++)
#pragma unroll
            for (int c = 0; c < 4; c++) acc[a][b][c] = 0.f;

    float4 ar[4];
    ldA(A, M, K, m0, 0, tid, ar);
    cpB(bs_addr, Bmat, Nld, n0, 0, tid);
    stA((__half2*)As, tid, ar);
    cp_commit();
    cp_wait0();
    __syncthreads();

    int nit = K / BK;
    for (int it = 0; it < nit; it++) {
        int cur = it & 1;
        const __half* Ac = As + cur * ABUF;
        const __half* Bc = Bs + cur * BBUF;
        if (it + 1 < nit) {
            ldA(A, M, K, m0, (it + 1) * BK, tid, ar);
            cpB(bs_addr + (cur ^ 1) * (BBUF * 2), Bmat, Nld, n0, (it + 1) * BK, tid);
            cp_commit();
        }

#pragma unroll
        for (int kc2 = 0; kc2 < 2; kc2++) {
            uint4 af[4];
#pragma unroll
            for (int tm = 0; tm < 4; tm++) {
                int mb = (wm >> 4) + tm;
                af[tm] = *(const uint4*)(Ac + (kc2 * 8 + mb) * 256 + lane * 8);
            }
            uint2 bf[4];
#pragma unroll
            for (int tn = 0; tn < 4; tn++) {
                int nb = (wn >> 3) + tn;
                bf[tn] = *(const uint2*)(Bc + (kc2 * 16 + nb) * 128 + lane * 4);
            }
#pragma unroll
            for (int tm = 0; tm < 4; tm++)
#pragma unroll
                for (int tn = 0; tn < 4; tn++)
                    mma_f16(acc[tm][tn], (const uint32_t*)&af[tm],
                            (const uint32_t*)&bf[tn]);
        }

        if (it + 1 < nit) stA((__half2*)(As + (cur ^ 1) * ABUF), tid, ar);
        cp_wait0();
        __syncthreads();
    }

    // epilogue: c0,c1 row g cols 2t,2t+1 ; c2,c3 row g+8
    int gg = lane >> 2, tt = lane & 3;
#pragma unroll
    for (int tm = 0; tm < 4; tm++) {
        int r0 = m0 + wm + tm * 16 + gg;
        int r1 = r0 + 8;
#pragma unroll
        for (int tn = 0; tn < 4; tn++) {
            int cb = n0 + wn + tn * 8 + 2 * tt;
            float b0 = __ldg(bias + cb);
            float b1 = __ldg(bias + cb + 1);
            float v00 = acc[tm][tn][0] + b0;
            float v01 = acc[tm][tn][1] + b1;
            float v10 = acc[tm][tn][2] + b0;
            float v11 = acc[tm][tn][3] + b1;
            if (ACT == 1) {
                v00 = fmaxf(v00, 0.f); v01 = fmaxf(v01, 0.f);
                v10 = fmaxf(v10, 0.f); v11 = fmaxf(v11, 0.f);
            }
            if (ACT == 2) {
                v00 = 0.5f * v00 * (1.f + erff(v00 * 0.70710678118654752f));
                v01 = 0.5f * v01 * (1.f + erff(v01 * 0.70710678118654752f));
                v10 = 0.5f * v10 * (1.f + erff(v10 * 0.70710678118654752f));
                v11 = 0.5f * v11 * (1.f + erff(v11 * 0.70710678118654752f));
            }
            if (r0 < M) *(float2*)(C + (size_t)r0 * Nld + cb) = make_float2(v00, v01);
            if (r1 < M) *(float2*)(C + (size_t)r1 * Nld + cb) = make_float2(v10, v11);
        }
    }
}

template <int ACT>
__global__ __launch_bounds__(256, 2) void gemm_f16(
    const float* __restrict__ A, const __half* __restrict__ B,
    const float* __restrict__ bias, float* __restrict__ C,
    int M, int K, int Nld) {
    __shared__ __align__(16) __half As[2 * ABUF];
    __shared__ __align__(16) __half Bs[2 * BBUF];
    uint32_t bs = (uint32_t)__cvta_generic_to_shared(Bs);
    gemm_core<ACT>(A, B, bias, C, M, K, Nld, blockIdx.x * BM, blockIdx.y * BN,
                   As, Bs, bs);
}

// fused Q/K/V/SK projection: grid.y in [0,4) selects operator
__global__ __launch_bounds__(256, 2) void gemm_qkvsk(
    const float* __restrict__ A, const __half* __restrict__ wt,
    const float* __restrict__ bq, const float* __restrict__ bk,
    const float* __restrict__ bv, const float* __restrict__ bsk, int l) {
    __shared__ __align__(16) __half As[2 * ABUF];
    __shared__ __align__(16) __half Bs[2 * BBUF];
    uint32_t bs = (uint32_t)__cvta_generic_to_shared(Bs);
    const __half* B;
    const float* bias;
    float* C;
    switch (blockIdx.y) {
        case 0: B = wt + OFF_WQ;  bias = bq;  C = g_q;  break;
        case 1: B = wt + OFF_WK;  bias = bk;  C = g_k;  break;
        case 2: B = wt + OFF_WV;  bias = bv;  C = g_v;  break;
        default: B = wt + OFF_WSK; bias = bsk; C = g_sk; break;
    }
    B += (size_t)l * HIDC * HIDC;
    bias += l * HIDC;
    gemm_core<0>(A, B, bias, C, NN, HIDC, HIDC, blockIdx.x * BM, 0, As, Bs, bs);
}

// ---- fused attention + LayerNorm1: warp/node; writes h = LN(z + attn + sk) ----
__global__ __launch_bounds__(256) void attn_ln_fused(
    const float* __restrict__ g, const float* __restrict__ bt) {
    int node = (blockIdx.x * blockDim.x + threadIdx.x) >> 5;
    if (node >= NN) return;
    int lane = threadIdx.x & 31;
    int beg = g_rowptr[node], end = g_rowptr[node + 1];
    size_t qb = (size_t)node * HIDC + lane * 4;
    float4 qv = *(const float4*)(g_q + qb);
    float m = -INFINITY, l = 0.f;
    float4 acc = make_float4(0.f, 0.f, 0.f, 0.f);
    int e = beg;
    for (; e + 1 < end; e += 2) {
        int s0 = g_csrc[e], s1 = g_csrc[e + 1];
        size_t b0 = (size_t)s0 * HIDC + lane * 4;
        size_t b1 = (size_t)s1 * HIDC + lane * 4;
        float4 k0 = *(const float4*)(g_k + b0);
        float4 k1 = *(const float4*)(g_k + b1);
        float4 v0 = *(const float4*)(g_v + b0);
        float4 v1 = *(const float4*)(g_v + b1);
        float p0 = qv.x * k0.x + qv.y * k0.y + qv.z * k0.z + qv.w * k0.w;
        float p1 = qv.x * k1.x + qv.y * k1.y + qv.z * k1.z + qv.w * k1.w;
        p0 += __shfl_xor_sync(0xffffffffu, p0, 8, 16);
        p1 += __shfl_xor_sync(0xffffffffu, p1, 8, 16);
        p0 += __shfl_xor_sync(0xffffffffu, p0, 4, 16);
        p1 += __shfl_xor_sync(0xffffffffu, p1, 4, 16);
        p0 += __shfl_xor_sync(0xffffffffu, p0, 2, 16);
        p1 += __shfl_xor_sync(0xffffffffu, p1, 2, 16);
        p0 += __shfl_xor_sync(0xffffffffu, p0, 1, 16);
        p1 += __shfl_xor_sync(0xffffffffu, p1, 1, 16);
        float sc0 = p0 * 0.125f;
        float sc1 = p1 * 0.125f;
        float mn = fmaxf(m, fmaxf(sc0, sc1));
        float scale = __expf(m - mn);
        float w0 = __expf(sc0 - mn);
        float w1 = __expf(sc1 - mn);
        l = l * scale + w0 + w1;
        acc.x = acc.x * scale + w0 * v0.x + w1 * v1.x;
        acc.y = acc.y * scale + w0 * v0.y + w1 * v1.y;
        acc.z = acc.z * scale + w0 * v0.z + w1 * v1.z;
        acc.w = acc.w * scale + w0 * v0.w + w1 * v1.w;
        m = mn;
    }
    if (e < end) {
        int s = g_csrc[e];
        size_t sb = (size_t)s * HIDC + lane * 4;
        float4 kv = *(const float4*)(g_k + sb);
        float4 vv = *(const float4*)(g_v + sb);
        float p = qv.x * kv.x + qv.y * kv.y + qv.z * kv.z + qv.w * kv.w;
        p += __shfl_xor_sync(0xffffffffu, p, 8, 16);
        p += __shfl_xor_sync(0xffffffffu, p, 4, 16);
        p += __shfl_xor_sync(0xffffffffu, p, 2, 16);
        p += __shfl_xor_sync(0xffffffffu, p, 1, 16);
        float sc = p * 0.125f;
        float mn = fmaxf(m, sc);
        float scale = __expf(m - mn);
        float w = __expf(sc - mn);
        l = l * scale + w;
        acc.x = acc.x * scale + w * vv.x;
        acc.y = acc.y * scale + w * vv.y;
        acc.z = acc.z * scale + w * vv.z;
        acc.w = acc.w * scale + w * vv.w;
    }
    float inv = (l > 0.f) ? 1.f / l : 0.f;
    acc.x *= inv; acc.y *= inv; acc.z *= inv; acc.w *= inv;

    // --- fused LayerNorm-1: h = LN(z + attn + sk) * g + bt ---
    float4 a = *(const float4*)(g_z + qb);
    float4 c = *(const float4*)(g_sk + qb);
    float v0 = a.x + acc.x + c.x, v1 = a.y + acc.y + c.y;
    float v2 = a.z + acc.z + c.z, v3 = a.w + acc.w + c.w;
    float s = v0 + v1 + v2 + v3;
#pragma unroll
    for (int o = 16; o > 0; o >>= 1) s += __shfl_xor_sync(0xffffffffu, s, o);
    float mu = s * (1.f / HIDC);
    float d0 = v0 - mu, d1 = v1 - mu, d2 = v2 - mu, d3 = v3 - mu;
    float ss = d0 * d0 + d1 * d1 + d2 * d2 + d3 * d3;
#pragma unroll
    for (int o = 16; o > 0; o >>= 1) ss += __shfl_xor_sync(0xffffffffu, ss, o);
    float rs = rsqrtf(ss * (1.f / HIDC) + EPSLN);
    int col = lane * 4;
    float4 o4;
    o4.x = d0 * rs * g[col + 0] + bt[col + 0];
    o4.y = d1 * rs * g[col + 1] + bt[col + 1];
    o4.z = d2 * rs * g[col + 2] + bt[col + 2];
    o4.w = d3 * rs * g[col + 3] + bt[col + 3];
    *(float4*)(g_h + qb) = o4;
}

// z = relu(LN(h+u)); out += betas[li]*z
__global__ __launch_bounds__(256) void lnacc_kernel(
    const float* __restrict__ g, const float* __restrict__ bt,
    float* __restrict__ out, int li) {
    int row = (blockIdx.x * blockDim.x + threadIdx.x) >> 5;
    if (row >= NN) return;
    int lane = threadIdx.x & 31;
    size_t base = (size_t)row * HIDC + lane * 4;
    float4 a = *(const float4*)(g_h + base);
    float4 b = *(const float4*)(g_u + base);
    float v0 = a.x + b.x, v1 = a.y + b.y, v2 = a.z + b.z, v3 = a.w + b.w;
    float s = v0 + v1 + v2 + v3;
#pragma unroll
    for (int o = 16; o > 0; o >>= 1) s += __shfl_xor_sync(0xffffffffu, s, o);
    float mu = s * (1.f / HIDC);
    float d0 = v0 - mu, d1 = v1 - mu, d2 = v2 - mu, d3 = v3 - mu;
    float ss = d0 * d0 + d1 * d1 + d2 * d2 + d3 * d3;
#pragma unroll
    for (int o = 16; o > 0; o >>= 1) ss += __shfl_xor_sync(0xffffffffu, ss, o);
    float rs = rsqrtf(ss * (1.f / HIDC) + EPSLN);
    int col = lane * 4;
    float z0 = fmaxf(d0 * rs * g[col + 0] + bt[col + 0], 0.f);
    float z1 = fmaxf(d1 * rs * g[col + 1] + bt[col + 1], 0.f);
    float z2 = fmaxf(d2 * rs * g[col + 2] + bt[col + 2], 0.f);
    float z3 = fmaxf(d3 * rs * g[col + 3] + bt[col + 3], 0.f);
    float bb = g_betas[li];
    *(float4*)(g_z + base) = make_float4(z0, z1, z2, z3);
    float4 oo = *(float4*)(out + base);
    oo.x += bb * z0; oo.y += bb * z1; oo.z += bb * z2; oo.w += bb * z3;
    *(float4*)(out + base) = oo;
}

__global__ __launch_bounds__(256) void init_acc(float* __restrict__ out) {
    int i = blockIdx.x * blockDim.x + threadIdx.x;
    if (i < NN * HIDC) out[i] = g_betas[0] * g_z[i];
}

// ---------------- host launcher ----------------
extern "C" void kernel_launch(void* const* d_in, const int* in_sizes, int n_in,
                              void* d_out, int out_size) {
    const float* x    = (const float*)d_in[0];
    const void*  ei   = d_in[1];
    const float* Win  = (const float*)d_in[2];
    const float* b_in = (const float*)d_in[3];
    const float* Wq   = (const float*)d_in[4];
    const float* bq   = (const float*)d_in[5];
    const float* Wk   = (const float*)d_in[6];
    const float* bk   = (const float*)d_in[7];
    const float* Wv   = (const float*)d_in[8];
    const float* bv   = (const float*)d_in[9];
    const float* Wsk  = (const float*)d_in[10];
    const float* bsk  = (const float*)d_in[11];
    const float* W1   = (const float*)d_in[12];
    const float* b1   = (const float*)d_in[13];
    const float* W2   = (const float*)d_in[14];
    const float* b2   = (const float*)d_in[15];
    const float* g1   = (const float*)d_in[16];
    const float* bt1  = (const float*)d_in[17];
    const float* g2   = (const float*)d_in[18];
    const float* bt2  = (const float*)d_in[19];
    const float* beta = (const float*)d_in[20];
    float* out = (float*)d_out;

    float *z, *h, *t, *u;
    __half* wt;
    cudaGetSymbolAddress((void**)&z, g_z);
    cudaGetSymbolAddress((void**)&h, g_h);
    cudaGetSymbolAddress((void**)&t, g_t);
    cudaGetSymbolAddress((void**)&u, g_u);
    cudaGetSymbolAddress((void**)&wt, g_wt);

    const int GM = (NN + BM - 1) / BM;  // 391

    // captures land on launch index 3 -> representative GEMM there
    sniff_kernel<<<1, 32>>>((const unsigned*)ei);                        // 0
    beta_softmax<<<1, 32>>>(beta);                                       // 1
    convW<<<(TOTW + 255) / 256, 256>>>(Win, Wq, Wk, Wv, Wsk, W1, W2);    // 2
    gemm_f16<1><<<dim3(GM, 1), 256>>>(x, wt, b_in, z, NN, HIDC, HIDC);   // 3
    gemm_qkvsk<<<dim3(GM, 4), 256>>>(z, wt, bq, bk, bv, bsk, 0);         // 4

    init_acc<<<(NN * HIDC + 255) / 256, 256>>>(out);
    convert_edges<<<(EE + 255) / 256, 256>>>(ei);

    // CSR build (once; needed before first attn)
    k_clear_deg<<<(NN + 255) / 256, 256>>>();
    k_hist<<<(EE + 255) / 256, 256>>>();
    k_chunksum<<<NCHK, CHUNK>>>();
    k_scanchunks<<<1, 32>>>();
    k_rowptr<<<NCHK, CHUNK>>>();
    k_fill<<<(EE + 255) / 256, 256>>>();

    for (int l = 0; l < NLAYERS; l++) {
        if (l > 0)
            gemm_qkvsk<<<dim3(GM, 4), 256>>>(z, wt, bq, bk, bv, bsk, l);

        attn_ln_fused<<<(NN * 32 + 255) / 256, 256>>>(g1 + l * HIDC, bt1 + l * HIDC);

        gemm_f16<2><<<dim3(GM, 2), 256>>>(h, wt + OFF_W1 + (size_t)l * HIDC * FFC,
                                          b1 + l * FFC, t, NN, HIDC, FFC);
        gemm_f16<0><<<dim3(GM, 1), 256>>>(t, wt + OFF_W2 + (size_t)l * FFC * HIDC,
                                          b2 + l * HIDC, u, NN, FFC, HIDC);

        lnacc_kernel<<<(NN + 7) / 8, 256>>>(g2 + l * HIDC, bt2 + l * HIDC, out, l + 1);
    }
}

// round 15
// speedup vs baseline: 1.2971x; 1.0056x over previous
#include <cuda_runtime.h>
#include <cuda_fp16.h>
#include <math.h>
#include <stdint.h>

#define NN 50000
#define EE 800000
#define HIDC 128
#define FFC 256
#define NLAYERS 6
#define EPSLN 1e-5f

// ---------------- scratch (device globals; no allocation allowed) ----------------
__device__ float g_z[NN * HIDC];
__device__ float g_q[NN * HIDC];
__device__ float g_k[NN * HIDC];
__device__ float g_v[NN * HIDC];
__device__ float g_sk[NN * HIDC];
__device__ float g_h[NN * HIDC];
__device__ float g_u[NN * HIDC];
__device__ int g_src[EE];
__device__ int g_dst[EE];
__device__ int g_deg[NN];
__device__ int g_rowptr[NN + 1];
__device__ int g_cur[NN];
__device__ int g_csrc[EE];
__device__ int g_csums[128];
__device__ float g_betas[NLAYERS + 2];
__device__ int g_flag[1];

// fp16-preconverted weights, FRAGMENT-MAJOR (m16n8k16) layout; element offsets
#define OFF_WQ  16384
#define OFF_WK  (OFF_WQ + NLAYERS * HIDC * HIDC)
#define OFF_WV  (OFF_WK + NLAYERS * HIDC * HIDC)
#define OFF_WSK (OFF_WV + NLAYERS * HIDC * HIDC)
#define OFF_W1  (OFF_WSK + NLAYERS * HIDC * HIDC)
#define OFF_W2  (OFF_W1 + NLAYERS * HIDC * FFC)
#define TOTW    (OFF_W2 + NLAYERS * FFC * HIDC)
__device__ __half g_wt[TOTW];

#define CHUNK 512
#define NCHK ((NN + CHUNK - 1) / CHUNK)   // 98

// ---------------- helpers ----------------
__device__ __forceinline__ void mma_f16(float* d, const uint32_t* a, const uint32_t* b) {
    asm volatile(
        "mma.sync.aligned.m16n8k16.row.col.f32.f16.f16.f32 "
        "{%0,%1,%2,%3}, {%4,%5,%6,%7}, {%8,%9}, {%0,%1,%2,%3};"
        : "+f"(d[0]), "+f"(d[1]), "+f"(d[2]), "+f"(d[3])
        : "r"(a[0]), "r"(a[1]), "r"(a[2]), "r"(a[3]), "r"(b[0]), "r"(b[1]));
}

__device__ __forceinline__ void cp16(uint32_t saddr, const void* g) {
    asm volatile("cp.async.ca.shared.global [%0], [%1], 16;" ::"r"(saddr), "l"(g));
}
__device__ __forceinline__ void cp_commit() { asm volatile("cp.async.commit_group;"); }
__device__ __forceinline__ void cp_wait0() { asm volatile("cp.async.wait_group 0;"); }

// ---------------- edge index dtype sniff + convert ----------------
__global__ void sniff_kernel(const unsigned* __restrict__ w) {
    if (threadIdx.x == 0 && blockIdx.x == 0) {
        int is64 = 1;
        for (int i = 1; i < 64; i += 2)
            if (w[i] != 0u) { is64 = 0; break; }
        g_flag[0] = is64;
    }
}

__global__ __launch_bounds__(256) void convert_edges(const void* __restrict__ ei) {
    int e = blockIdx.x * blockDim.x + threadIdx.x;
    if (e >= EE) return;
    if (g_flag[0]) {
        const long long* p = (const long long*)ei;
        g_src[e] = (int)p[e];
        g_dst[e] = (int)p[EE + e];
    } else {
        const int* p = (const int*)ei;
        g_src[e] = p[e];
        g_dst[e] = p[EE + e];
    }
}

__global__ void beta_softmax(const float* __restrict__ beta) {
    if (threadIdx.x == 0 && blockIdx.x == 0) {
        float m = -1e30f;
        for (int i = 0; i < NLAYERS + 1; i++) m = fmaxf(m, beta[i]);
        float s = 0.f;
        for (int i = 0; i < NLAYERS + 1; i++) {
            float e = expf(beta[i] - m);
            g_betas[i] = e;
            s += e;
        }
        for (int i = 0; i < NLAYERS + 1; i++) g_betas[i] /= s;
    }
}

// ---------------- weight fp16 convert + m16n8k16 fragment-major permute -------
__device__ __forceinline__ int permW16(int k, int n, int N) {
    return (k >> 4) * 16 * N + (n >> 3) * 128 +
           ((n & 7) * 4 + ((k & 7) >> 1)) * 4 + ((k >> 3) & 1) * 2 + (k & 1);
}

__global__ __launch_bounds__(256) void convW(
    const float* __restrict__ Win, const float* __restrict__ Wq,
    const float* __restrict__ Wk, const float* __restrict__ Wv,
    const float* __restrict__ Wsk, const float* __restrict__ W1,
    const float* __restrict__ W2) {
    int i = blockIdx.x * blockDim.x + threadIdx.x;
    if (i >= TOTW) return;
    const float* src;
    int base, off, N, matsz;
    if (i < OFF_WQ)       { src = Win; base = 0;       off = i;           N = 128; matsz = HIDC * HIDC; }
    else if (i < OFF_WK)  { src = Wq;  base = OFF_WQ;  off = i - OFF_WQ;  N = 128; matsz = HIDC * HIDC; }
    else if (i < OFF_WV)  { src = Wk;  base = OFF_WK;  off = i - OFF_WK;  N = 128; matsz = HIDC * HIDC; }
    else if (i < OFF_WSK) { src = Wv;  base = OFF_WV;  off = i - OFF_WV;  N = 128; matsz = HIDC * HIDC; }
    else if (i < OFF_W1)  { src = Wsk; base = OFF_WSK; off = i - OFF_WSK; N = 128; matsz = HIDC * HIDC; }
    else if (i < OFF_W2)  { src = W1;  base = OFF_W1;  off = i - OFF_W1;  N = 256; matsz = HIDC * FFC; }
    else                  { src = W2;  base = OFF_W2;  off = i - OFF_W2;  N = 128; matsz = FFC * HIDC; }
    int l = off / matsz;
    int o2 = off - l * matsz;
    int k = o2 / N, n = o2 - k * N;
    g_wt[base + l * matsz + permW16(k, n, N)] = __float2half_rn(src[off]);
}

// ---------------- CSR build ----------------
__global__ __launch_bounds__(256) void k_clear_deg() {
    int i = blockIdx.x * blockDim.x + threadIdx.x;
    if (i < NN) g_deg[i] = 0;
}
__global__ __launch_bounds__(256) void k_hist() {
    int e = blockIdx.x * blockDim.x + threadIdx.x;
    if (e < EE) atomicAdd(&g_deg[g_dst[e]], 1);
}
__global__ __launch_bounds__(CHUNK) void k_chunksum() {
    __shared__ int sh[CHUNK];
    int tid = threadIdx.x;
    int i = blockIdx.x * CHUNK + tid;
    sh[tid] = (i < NN) ? g_deg[i] : 0;
    __syncthreads();
    for (int off = CHUNK / 2; off > 0; off >>= 1) {
        if (tid < off) sh[tid] += sh[tid + off];
        __syncthreads();
    }
    if (tid == 0) g_csums[blockIdx.x] = sh[0];
}
__global__ void k_scanchunks() {
    if (threadIdx.x == 0 && blockIdx.x == 0) {
        int run = 0;
        for (int c = 0; c < NCHK; c++) {
            int v = g_csums[c];
            g_csums[c] = run;
            run += v;
        }
        g_rowptr[NN] = run;
    }
}
__global__ __launch_bounds__(CHUNK) void k_rowptr() {
    __shared__ int sh[CHUNK];
    int tid = threadIdx.x;
    int i = blockIdx.x * CHUNK + tid;
    int v = (i < NN) ? g_deg[i] : 0;
    sh[tid] = v;
    __syncthreads();
    for (int off = 1; off < CHUNK; off <<= 1) {
        int t = (tid >= off) ? sh[tid - off] : 0;
        __syncthreads();
        sh[tid] += t;
        __syncthreads();
    }
    if (i < NN) {
        int excl = sh[tid] - v + g_csums[blockIdx.x];
        g_rowptr[i] = excl;
        g_cur[i] = excl;
    }
}
__global__ __launch_bounds__(256) void k_fill() {
    int e = blockIdx.x * blockDim.x + threadIdx.x;
    if (e >= EE) return;
    int slot = atomicAdd(&g_cur[g_dst[e]], 1);
    g_csrc[slot] = g_src[e];
}

// ---------------- FP16 GEMM (m16n8k16), BK=32, fragment-major smem -----------
#define BM 128
#define BN 128
#define BK 32
#define ABUF 4096   // halves per A buffer
#define BBUF 4096   // halves per B buffer

__device__ __forceinline__ void ldA(
    const float* __restrict__ A, int M, int K, int m0, int kc, int tid,
    float4 ar[4]) {
#pragma unroll
    for (int i = 0; i < 4; i++) {
        int f = tid + i * 256;
        int m = f >> 3, k4 = (f & 7) * 4;
        ar[i] = (m0 + m < M)
                    ? *(const float4*)(A + (size_t)(m0 + m) * K + kc + k4)
                    : make_float4(0.f, 0.f, 0.f, 0.f);
    }
}

__device__ __forceinline__ void stA(__half2* As2, int tid, const float4 ar[4]) {
#pragma unroll
    for (int i = 0; i < 4; i++) {
        int f = tid + i * 256;
        int m = f >> 3, k4 = (f & 7) * 4;
        int kc2 = k4 >> 4, k4r = k4 & 15;
        int g = m & 7, h = (m >> 3) & 1, mb = m >> 4;
        int t = (k4r & 7) >> 1;            // 0 or 2
        int kb = (k4r >> 3) & 1;
        int reg = h + 2 * kb;
        int cb = (kc2 * 8 + mb) * 128;     // chunk base in half2
        __half2 p0 = __floats2half2_rn(ar[i].x, ar[i].y);
        __half2 p1 = __floats2half2_rn(ar[i].z, ar[i].w);
        As2[cb + (g * 4 + t) * 4 + reg] = p0;
        As2[cb + (g * 4 + t + 1) * 4 + reg] = p1;
    }
}

__device__ __forceinline__ void cpB(uint32_t bs_addr, const __half* __restrict__ Bmat,
                                    int N, int n0, int kc, int tid) {
    const __half* gp0 = Bmat + (size_t)kc * N + (n0 >> 3) * 128;
    const __half* gp1 = Bmat + (size_t)(kc + 16) * N + (n0 >> 3) * 128;
#pragma unroll
    for (int i = 0; i < 2; i++) {
        int idx = tid + i * 256;           // 0..511
        const __half* gp = (idx < 256) ? (gp0 + idx * 8) : (gp1 + (idx - 256) * 8);
        cp16(bs_addr + idx * 16, gp);
    }
}

template <int ACT>
__device__ __forceinline__ void gemm_core(
    const float* __restrict__ A, const __half* __restrict__ Bmat,
    const float* __restrict__ bias, float* __restrict__ C,
    int M, int K, int Nld, int m0, int n0,
    __half* As, __half* Bs, uint32_t bs_addr) {
    int tid = threadIdx.x;
    int warp = tid >> 5, lane = tid & 31;
    int wm = (warp >> 2) * 64, wn = (warp & 3) * 32;

    float acc[4][4][4];
#pragma unroll
    for (int a = 0; a < 4; a++)
#pragma unroll
        for (int b = 0; b < 4; b++)
#pragma unroll
            for (int c = 0; c < 4; c++) acc[a][b][c] = 0.f;

    float4 ar[4];
    ldA(A, M, K, m0, 0, tid, ar);
    cpB(bs_addr, Bmat, Nld, n0, 0, tid);
    stA((__half2*)As, tid, ar);
    cp_commit();
    cp_wait0();
    __syncthreads();

    int nit = K / BK;
    for (int it = 0; it < nit; it++) {
        int cur = it & 1;
        const __half* Ac = As + cur * ABUF;
        const __half* Bc = Bs + cur * BBUF;
        if (it + 1 < nit) {
            ldA(A, M, K, m0, (it + 1) * BK, tid, ar);
            cpB(bs_addr + (cur ^ 1) * (BBUF * 2), Bmat, Nld, n0, (it + 1) * BK, tid);
            cp_commit();
        }

#pragma unroll
        for (int kc2 = 0; kc2 < 2; kc2++) {
            uint4 af[4];
#pragma unroll
            for (int tm = 0; tm < 4; tm++) {
                int mb = (wm >> 4) + tm;
                af[tm] = *(const uint4*)(Ac + (kc2 * 8 + mb) * 256 + lane * 8);
            }
            uint2 bf[4];
#pragma unroll
            for (int tn = 0; tn < 4; tn++) {
                int nb = (wn >> 3) + tn;
                bf[tn] = *(const uint2*)(Bc + (kc2 * 16 + nb) * 128 + lane * 4);
            }
#pragma unroll
            for (int tm = 0; tm < 4; tm++)
#pragma unroll
                for (int tn = 0; tn < 4; tn++)
                    mma_f16(acc[tm][tn], (const uint32_t*)&af[tm],
                            (const uint32_t*)&bf[tn]);
        }

        if (it + 1 < nit) stA((__half2*)(As + (cur ^ 1) * ABUF), tid, ar);
        cp_wait0();
        __syncthreads();
    }

    // epilogue
    int gg = lane >> 2, tt = lane & 3;
#pragma unroll
    for (int tm = 0; tm < 4; tm++) {
        int r0 = m0 + wm + tm * 16 + gg;
        int r1 = r0 + 8;
#pragma unroll
        for (int tn = 0; tn < 4; tn++) {
            int cb = n0 + wn + tn * 8 + 2 * tt;
            float b0 = __ldg(bias + cb);
            float b1 = __ldg(bias + cb + 1);
            float v00 = acc[tm][tn][0] + b0;
            float v01 = acc[tm][tn][1] + b1;
            float v10 = acc[tm][tn][2] + b0;
            float v11 = acc[tm][tn][3] + b1;
            if (ACT == 1) {
                v00 = fmaxf(v00, 0.f); v01 = fmaxf(v01, 0.f);
                v10 = fmaxf(v10, 0.f); v11 = fmaxf(v11, 0.f);
            }
            if (r0 < M) *(float2*)(C + (size_t)r0 * Nld + cb) = make_float2(v00, v01);
            if (r1 < M) *(float2*)(C + (size_t)r1 * Nld + cb) = make_float2(v10, v11);
        }
    }
}

template <int ACT>
__global__ __launch_bounds__(256, 2) void gemm_f16(
    const float* __restrict__ A, const __half* __restrict__ B,
    const float* __restrict__ bias, float* __restrict__ C,
    int M, int K, int Nld) {
    __shared__ __align__(16) __half As[2 * ABUF];
    __shared__ __align__(16) __half Bs[2 * BBUF];
    uint32_t bs = (uint32_t)__cvta_generic_to_shared(Bs);
    gemm_core<ACT>(A, B, bias, C, M, K, Nld, blockIdx.x * BM, blockIdx.y * BN,
                   As, Bs, bs);
}

// fused Q/K/V/SK projection: grid.y in [0,4) selects operator
__global__ __launch_bounds__(256, 2) void gemm_qkvsk(
    const float* __restrict__ A, const __half* __restrict__ wt,
    const float* __restrict__ bq, const float* __restrict__ bk,
    const float* __restrict__ bv, const float* __restrict__ bsk, int l) {
    __shared__ __align__(16) __half As[2 * ABUF];
    __shared__ __align__(16) __half Bs[2 * BBUF];
    uint32_t bs = (uint32_t)__cvta_generic_to_shared(Bs);
    const __half* B;
    const float* bias;
    float* C;
    switch (blockIdx.y) {
        case 0: B = wt + OFF_WQ;  bias = bq;  C = g_q;  break;
        case 1: B = wt + OFF_WK;  bias = bk;  C = g_k;  break;
        case 2: B = wt + OFF_WV;  bias = bv;  C = g_v;  break;
        default: B = wt + OFF_WSK; bias = bsk; C = g_sk; break;
    }
    B += (size_t)l * HIDC * HIDC;
    bias += l * HIDC;
    gemm_core<0>(A, B, bias, C, NN, HIDC, HIDC, blockIdx.x * BM, 0, As, Bs, bs);
}

// ---------------- fused FFN: u = gelu(h@W1+b1) @ W2 + b2, t kept in smem ------
// dynamic smem: tS 32768 halves (64KB, A-frag layout for K=256) |
//               As 8192 halves (16KB) | Bs 8192 halves (16KB)   = 96KB
__global__ __launch_bounds__(256) void ffn_fused(
    const float* __restrict__ h, const __half* __restrict__ W1f,
    const float* __restrict__ b1, const __half* __restrict__ W2f,
    const float* __restrict__ b2, float* __restrict__ u) {
    extern __shared__ __half dsm[];
    __half* tS = dsm;                 // 32768 halves
    __half* As = dsm + 32768;         // 8192
    __half* Bs = dsm + 40960;         // 8192
    uint32_t bs = (uint32_t)__cvta_generic_to_shared(Bs);
    __half2* tS2 = (__half2*)tS;

    int tid = threadIdx.x;
    int warp = tid >> 5, lane = tid & 31;
    int wm = (warp >> 2) * 64, wn = (warp & 3) * 32;
    int gg = lane >> 2, tt = lane & 3;
    int m0 = blockIdx.x * BM;

    // ---------------- phase 1: t = gelu(h @ W1 + b1), two 128-N tiles --------
    for (int half_n = 0; half_n < 2; half_n++) {
        int n0 = half_n * 128;
        float acc[4][4][4];
#pragma unroll
        for (int a = 0; a < 4; a++)
#pragma unroll
            for (int b = 0; b < 4; b++)
#pragma unroll
                for (int c = 0; c < 4; c++) acc[a][b][c] = 0.f;

        float4 ar[4];
        ldA(h, NN, HIDC, m0, 0, tid, ar);
        cpB(bs, W1f, FFC, n0, 0, tid);
        stA((__half2*)As, tid, ar);
        cp_commit();
        cp_wait0();
        __syncthreads();

        for (int it = 0; it < HIDC / BK; it++) {   // 4 iters
            int cur = it & 1;
            const __half* Ac = As + cur * ABUF;
            const __half* Bc = Bs + cur * BBUF;
            if (it + 1 < HIDC / BK) {
                ldA(h, NN, HIDC, m0, (it + 1) * BK, tid, ar);
                cpB(bs + (cur ^ 1) * (BBUF * 2), W1f, FFC, n0, (it + 1) * BK, tid);
                cp_commit();
            }
#pragma unroll
            for (int kc2 = 0; kc2 < 2; kc2++) {
                uint4 af[4];
#pragma unroll
                for (int tm = 0; tm < 4; tm++) {
                    int mb = (wm >> 4) + tm;
                    af[tm] = *(const uint4*)(Ac + (kc2 * 8 + mb) * 256 + lane * 8);
                }
                uint2 bf[4];
#pragma unroll
                for (int tn = 0; tn < 4; tn++) {
                    int nb = (wn >> 3) + tn;
                    bf[tn] = *(const uint2*)(Bc + (kc2 * 16 + nb) * 128 + lane * 4);
                }
#pragma unroll
                for (int tm = 0; tm < 4; tm++)
#pragma unroll
                    for (int tn = 0; tn < 4; tn++)
                        mma_f16(acc[tm][tn], (const uint32_t*)&af[tm],
                                (const uint32_t*)&bf[tn]);
            }
            if (it + 1 < HIDC / BK) stA((__half2*)(As + (cur ^ 1) * ABUF), tid, ar);
            cp_wait0();
            __syncthreads();
        }

        // epilogue: gelu, write to tS in A-fragment layout (K dim = t column)
#pragma unroll
        for (int tm = 0; tm < 4; tm++) {
            int mloc0 = wm + tm * 16 + gg;     // local rows
            int mloc1 = mloc0 + 8;
#pragma unroll
            for (int tn = 0; tn < 4; tn++) {
                int cb = n0 + wn + tn * 8 + 2 * tt;   // t column (0..255), even
                float b0 = __ldg(b1 + cb);
                float b1v = __ldg(b1 + cb + 1);
                float v00 = acc[tm][tn][0] + b0;
                float v01 = acc[tm][tn][1] + b1v;
                float v10 = acc[tm][tn][2] + b0;
                float v11 = acc[tm][tn][3] + b1v;
                v00 = 0.5f * v00 * (1.f + erff(v00 * 0.70710678118654752f));
                v01 = 0.5f * v01 * (1.f + erff(v01 * 0.70710678118654752f));
                v10 = 0.5f * v10 * (1.f + erff(v10 * 0.70710678118654752f));
                v11 = 0.5f * v11 * (1.f + erff(v11 * 0.70710678118654752f));
                int iter = cb >> 4, kk = cb & 15;
                int slot = (kk & 7) >> 1, kb = (kk >> 3) & 1;
                // row mloc0
                {
                    int g = mloc0 & 7, hh = (mloc0 >> 3) & 1, mb = mloc0 >> 4;
                    tS2[iter * 1024 + mb * 128 + (g * 4 + slot) * 4 + hh + 2 * kb] =
                        __floats2half2_rn(v00, v01);
                }
                // row mloc1
                {
                    int g = mloc1 & 7, hh = (mloc1 >> 3) & 1, mb = mloc1 >> 4;
                    tS2[iter * 1024 + mb * 128 + (g * 4 + slot) * 4 + hh + 2 * kb] =
                        __floats2half2_rn(v10, v11);
                }
            }
        }
        __syncthreads();
    }

    // ---------------- phase 2: u = t @ W2 + b2 (A from tS, K=256) ------------
    float acc[4][4][4];
#pragma unroll
    for (int a = 0; a < 4; a++)
#pragma unroll
        for (int b = 0; b < 4; b++)
#pragma unroll
            for (int c = 0; c < 4; c++) acc[a][b][c] = 0.f;

    cpB(bs, W2f, HIDC, 0, 0, tid);
    cp_commit();
    cp_wait0();
    __syncthreads();

    for (int it = 0; it < FFC / BK; it++) {   // 8 iters
        int cur = it & 1;
        const __half* Bc = Bs + cur * BBUF;
        if (it + 1 < FFC / BK) {
            cpB(bs + (cur ^ 1) * (BBUF * 2), W2f, HIDC, 0, (it + 1) * BK, tid);
            cp_commit();
        }
#pragma unroll
        for (int kc2 = 0; kc2 < 2; kc2++) {
            int iter = it * 2 + kc2;          // k16-iter in tS
            uint4 af[4];
#pragma unroll
            for (int tm = 0; tm < 4; tm++) {
                int mb = (wm >> 4) + tm;
                af[tm] = *(const uint4*)(tS + iter * 2048 + mb * 256 + lane * 8);
            }
            uint2 bf[4];
#pragma unroll
            for (int tn = 0; tn < 4; tn++) {
                int nb = (wn >> 3) + tn;
                bf[tn] = *(const uint2*)(Bc + (kc2 * 16 + nb) * 128 + lane * 4);
            }
#pragma unroll
            for (int tm = 0; tm < 4; tm++)
#pragma unroll
                for (int tn = 0; tn < 4; tn++)
                    mma_f16(acc[tm][tn], (const uint32_t*)&af[tm],
                            (const uint32_t*)&bf[tn]);
        }
        cp_wait0();
        __syncthreads();
    }

#pragma unroll
    for (int tm = 0; tm < 4; tm++) {
        int r0 = m0 + wm + tm * 16 + gg;
        int r1 = r0 + 8;
#pragma unroll
        for (int tn = 0; tn < 4; tn++) {
            int cb = wn + tn * 8 + 2 * tt;
            float b0 = __ldg(b2 + cb);
            float b1v = __ldg(b2 + cb + 1);
            float v00 = acc[tm][tn][0] + b0;
            float v01 = acc[tm][tn][1] + b1v;
            float v10 = acc[tm][tn][2] + b0;
            float v11 = acc[tm][tn][3] + b1v;
            if (r0 < NN) *(float2*)(u + (size_t)r0 * HIDC + cb) = make_float2(v00, v01);
            if (r1 < NN) *(float2*)(u + (size_t)r1 * HIDC + cb) = make_float2(v10, v11);
        }
    }
}

// ---- fused attention + LayerNorm1: warp/node; writes h = LN(z + attn + sk) ----
__global__ __launch_bounds__(256) void attn_ln_fused(
    const float* __restrict__ g, const float* __restrict__ bt) {
    int node = (blockIdx.x * blockDim.x + threadIdx.x) >> 5;
    if (node >= NN) return;
    int lane = threadIdx.x & 31;
    int beg = g_rowptr[node], end = g_rowptr[node + 1];
    size_t qb = (size_t)node * HIDC + lane * 4;
    float4 qv = *(const float4*)(g_q + qb);
    float m = -INFINITY, l = 0.f;
    float4 acc = make_float4(0.f, 0.f, 0.f, 0.f);
    int e = beg;
    for (; e + 1 < end; e += 2) {
        int s0 = g_csrc[e], s1 = g_csrc[e + 1];
        size_t b0 = (size_t)s0 * HIDC + lane * 4;
        size_t b1 = (size_t)s1 * HIDC + lane * 4;
        float4 k0 = *(const float4*)(g_k + b0);
        float4 k1 = *(const float4*)(g_k + b1);
        float4 v0 = *(const float4*)(g_v + b0);
        float4 v1 = *(const float4*)(g_v + b1);
        float p0 = qv.x * k0.x + qv.y * k0.y + qv.z * k0.z + qv.w * k0.w;
        float p1 = qv.x * k1.x + qv.y * k1.y + qv.z * k1.z + qv.w * k1.w;
        p0 += __shfl_xor_sync(0xffffffffu, p0, 8, 16);
        p1 += __shfl_xor_sync(0xffffffffu, p1, 8, 16);
        p0 += __shfl_xor_sync(0xffffffffu, p0, 4, 16);
        p1 += __shfl_xor_sync(0xffffffffu, p1, 4, 16);
        p0 += __shfl_xor_sync(0xffffffffu, p0, 2, 16);
        p1 += __shfl_xor_sync(0xffffffffu, p1, 2, 16);
        p0 += __shfl_xor_sync(0xffffffffu, p0, 1, 16);
        p1 += __shfl_xor_sync(0xffffffffu, p1, 1, 16);
        float sc0 = p0 * 0.125f;
        float sc1 = p1 * 0.125f;
        float mn = fmaxf(m, fmaxf(sc0, sc1));
        float scale = __expf(m - mn);
        float w0 = __expf(sc0 - mn);
        float w1 = __expf(sc1 - mn);
        l = l * scale + w0 + w1;
        acc.x = acc.x * scale + w0 * v0.x + w1 * v1.x;
        acc.y = acc.y * scale + w0 * v0.y + w1 * v1.y;
        acc.z = acc.z * scale + w0 * v0.z + w1 * v1.z;
        acc.w = acc.w * scale + w0 * v0.w + w1 * v1.w;
        m = mn;
    }
    if (e < end) {
        int s = g_csrc[e];
        size_t sb = (size_t)s * HIDC + lane * 4;
        float4 kv = *(const float4*)(g_k + sb);
        float4 vv = *(const float4*)(g_v + sb);
        float p = qv.x * kv.x + qv.y * kv.y + qv.z * kv.z + qv.w * kv.w;
        p += __shfl_xor_sync(0xffffffffu, p, 8, 16);
        p += __shfl_xor_sync(0xffffffffu, p, 4, 16);
        p += __shfl_xor_sync(0xffffffffu, p, 2, 16);
        p += __shfl_xor_sync(0xffffffffu, p, 1, 16);
        float sc = p * 0.125f;
        float mn = fmaxf(m, sc);
        float scale = __expf(m - mn);
        float w = __expf(sc - mn);
        l = l * scale + w;
        acc.x = acc.x * scale + w * vv.x;
        acc.y = acc.y * scale + w * vv.y;
        acc.z = acc.z * scale + w * vv.z;
        acc.w = acc.w * scale + w * vv.w;
    }
    float inv = (l > 0.f) ? 1.f / l : 0.f;
    acc.x *= inv; acc.y *= inv; acc.z *= inv; acc.w *= inv;

    // --- fused LayerNorm-1: h = LN(z + attn + sk) * g + bt ---
    float4 a = *(const float4*)(g_z + qb);
    float4 c = *(const float4*)(g_sk + qb);
    float v0 = a.x + acc.x + c.x, v1 = a.y + acc.y + c.y;
    float v2 = a.z + acc.z + c.z, v3 = a.w + acc.w + c.w;
    float s = v0 + v1 + v2 + v3;
#pragma unroll
    for (int o = 16; o > 0; o >>= 1) s += __shfl_xor_sync(0xffffffffu, s, o);
    float mu = s * (1.f / HIDC);
    float d0 = v0 - mu, d1 = v1 - mu, d2 = v2 - mu, d3 = v3 - mu;
    float ss = d0 * d0 + d1 * d1 + d2 * d2 + d3 * d3;
#pragma unroll
    for (int o = 16; o > 0; o >>= 1) ss += __shfl_xor_sync(0xffffffffu, ss, o);
    float rs = rsqrtf(ss * (1.f / HIDC) + EPSLN);
    int col = lane * 4;
    float4 o4;
    o4.x = d0 * rs * g[col + 0] + bt[col + 0];
    o4.y = d1 * rs * g[col + 1] + bt[col + 1];
    o4.z = d2 * rs * g[col + 2] + bt[col + 2];
    o4.w = d3 * rs * g[col + 3] + bt[col + 3];
    *(float4*)(g_h + qb) = o4;
}

// z = relu(LN(h+u)); out += betas[li]*z
__global__ __launch_bounds__(256) void lnacc_kernel(
    const float* __restrict__ g, const float* __restrict__ bt,
    float* __restrict__ out, int li) {
    int row = (blockIdx.x * blockDim.x + threadIdx.x) >> 5;
    if (row >= NN) return;
    int lane = threadIdx.x & 31;
    size_t base = (size_t)row * HIDC + lane * 4;
    float4 a = *(const float4*)(g_h + base);
    float4 b = *(const float4*)(g_u + base);
    float v0 = a.x + b.x, v1 = a.y + b.y, v2 = a.z + b.z, v3 = a.w + b.w;
    float s = v0 + v1 + v2 + v3;
#pragma unroll
    for (int o = 16; o > 0; o >>= 1) s += __shfl_xor_sync(0xffffffffu, s, o);
    float mu = s * (1.f / HIDC);
    float d0 = v0 - mu, d1 = v1 - mu, d2 = v2 - mu, d3 = v3 - mu;
    float ss = d0 * d0 + d1 * d1 + d2 * d2 + d3 * d3;
#pragma unroll
    for (int o = 16; o > 0; o >>= 1) ss += __shfl_xor_sync(0xffffffffu, ss, o);
    float rs = rsqrtf(ss * (1.f / HIDC) + EPSLN);
    int col = lane * 4;
    float z0 = fmaxf(d0 * rs * g[col + 0] + bt[col + 0], 0.f);
    float z1 = fmaxf(d1 * rs * g[col + 1] + bt[col + 1], 0.f);
    float z2 = fmaxf(d2 * rs * g[col + 2] + bt[col + 2], 0.f);
    float z3 = fmaxf(d3 * rs * g[col + 3] + bt[col + 3], 0.f);
    float bb = g_betas[li];
    *(float4*)(g_z + base) = make_float4(z0, z1, z2, z3);
    float4 oo = *(float4*)(out + base);
    oo.x += bb * z0; oo.y += bb * z1; oo.z += bb * z2; oo.w += bb * z3;
    *(float4*)(out + base) = oo;
}

__global__ __launch_bounds__(256) void init_acc(float* __restrict__ out) {
    int i = blockIdx.x * blockDim.x + threadIdx.x;
    if (i < NN * HIDC) out[i] = g_betas[0] * g_z[i];
}

// ---------------- host launcher ----------------
extern "C" void kernel_launch(void* const* d_in, const int* in_sizes, int n_in,
                              void* d_out, int out_size) {
    const float* x    = (const float*)d_in[0];
    const void*  ei   = d_in[1];
    const float* Win  = (const float*)d_in[2];
    const float* b_in = (const float*)d_in[3];
    const float* Wq   = (const float*)d_in[4];
    const float* bq   = (const float*)d_in[5];
    const float* Wk   = (const float*)d_in[6];
    const float* bk   = (const float*)d_in[7];
    const float* Wv   = (const float*)d_in[8];
    const float* bv   = (const float*)d_in[9];
    const float* Wsk  = (const float*)d_in[10];
    const float* bsk  = (const float*)d_in[11];
    const float* W1   = (const float*)d_in[12];
    const float* b1   = (const float*)d_in[13];
    const float* W2   = (const float*)d_in[14];
    const float* b2   = (const float*)d_in[15];
    const float* g1   = (const float*)d_in[16];
    const float* bt1  = (const float*)d_in[17];
    const float* g2   = (const float*)d_in[18];
    const float* bt2  = (const float*)d_in[19];
    const float* beta = (const float*)d_in[20];
    float* out = (float*)d_out;

    float *z, *h, *u;
    __half* wt;
    cudaGetSymbolAddress((void**)&z, g_z);
    cudaGetSymbolAddress((void**)&h, g_h);
    cudaGetSymbolAddress((void**)&u, g_u);
    cudaGetSymbolAddress((void**)&wt, g_wt);

    const int FFN_SMEM = 98304;
    cudaFuncSetAttribute(ffn_fused, cudaFuncAttributeMaxDynamicSharedMemorySize,
                         FFN_SMEM);

    const int GM = (NN + BM - 1) / BM;  // 391

    // captures land on launch index 3 -> representative GEMM there
    sniff_kernel<<<1, 32>>>((const unsigned*)ei);                        // 0
    beta_softmax<<<1, 32>>>(beta);                                       // 1
    convW<<<(TOTW + 255) / 256, 256>>>(Win, Wq, Wk, Wv, Wsk, W1, W2);    // 2
    gemm_f16<1><<<dim3(GM, 1), 256>>>(x, wt, b_in, z, NN, HIDC, HIDC);   // 3
    gemm_qkvsk<<<dim3(GM, 4), 256>>>(z, wt, bq, bk, bv, bsk, 0);         // 4

    init_acc<<<(NN * HIDC + 255) / 256, 256>>>(out);
    convert_edges<<<(EE + 255) / 256, 256>>>(ei);

    // CSR build (once; needed before first attn)
    k_clear_deg<<<(NN + 255) / 256, 256>>>();
    k_hist<<<(EE + 255) / 256, 256>>>();
    k_chunksum<<<NCHK, CHUNK>>>();
    k_scanchunks<<<1, 32>>>();
    k_rowptr<<<NCHK, CHUNK>>>();
    k_fill<<<(EE + 255) / 256, 256>>>();

    for (int l = 0; l < NLAYERS; l++) {
        if (l > 0)
            gemm_qkvsk<<<dim3(GM, 4), 256>>>(z, wt, bq, bk, bv, bsk, l);

        attn_ln_fused<<<(NN * 32 + 255) / 256, 256>>>(g1 + l * HIDC, bt1 + l * HIDC);

        ffn_fused<<<GM, 256, FFN_SMEM>>>(
            h, wt + OFF_W1 + (size_t)l * HIDC * FFC, b1 + l * FFC,
            wt + OFF_W2 + (size_t)l * FFC * HIDC, b2 + l * HIDC, u);

        lnacc_kernel<<<(NN + 7) / 8, 256>>>(g2 + l * HIDC, bt2 + l * HIDC, out, l + 1);
    }
}